// round 3
// baseline (speedup 1.0000x reference)
#include <cuda_runtime.h>
#include <math.h>

// ---------------- problem constants ----------------
#define D_MODEL  1024
#define NHEADS   16
#define HDIM     64
#define NTOK     2048
#define BATCH    2
#define MROWS    (BATCH*NTOK)       // 4096
#define QKVCOLS  (3*D_MODEL)        // 3072

// ---------------- scratch ----------------
__device__ float g_qkv[3*BATCH*NHEADS*NTOK*HDIM]; // [which][B][H][N][D]
__device__ float g_att[MROWS*D_MODEL];            // [B*N][H*D]
__device__ float g_cos[NTOK*HDIM];
__device__ float g_sin[NTOK*HDIM];
__device__ float g_xs [NTOK*HDIM];

// ---------------- helpers ----------------
__device__ __forceinline__ unsigned f2tf(float f) {
    unsigned u;
    asm("cvt.rna.tf32.f32 %0, %1;" : "=r"(u) : "f"(f));
    return u;
}
__device__ __forceinline__ void mma8(float c[4], const unsigned a[4], unsigned b0, unsigned b1) {
    asm("mma.sync.aligned.m16n8k8.row.col.f32.tf32.tf32.f32 "
        "{%0,%1,%2,%3},{%4,%5,%6,%7},{%8,%9},{%0,%1,%2,%3};"
        : "+f"(c[0]), "+f"(c[1]), "+f"(c[2]), "+f"(c[3])
        : "r"(a[0]), "r"(a[1]), "r"(a[2]), "r"(a[3]), "r"(b0), "r"(b1));
}
__device__ __forceinline__ void cpa16(unsigned dst, const void* src) {
    asm volatile("cp.async.cg.shared.global [%0], [%1], 16;" :: "r"(dst), "l"(src));
}
__device__ __forceinline__ void cpa_commit() {
    asm volatile("cp.async.commit_group;");
}
template<int N>
__device__ __forceinline__ void cpa_wait() {
    asm volatile("cp.async.wait_group %0;" :: "n"(N));
}

// ============================================================
// Kernel 1: xpos/ND-RoPE tables (fp64, matches numpy ref)
// ============================================================
__global__ void rope_tables_kernel() {
    int idx = blockIdx.x * blockDim.x + threadIdx.x;
    if (idx >= NTOK*HDIM) return;
    int n = idx >> 6;
    int d = idx & 63;
    int axis = d >> 5;
    int jj   = d & 31;
    int p    = jj >> 1;
    double t, half;
    if (axis == 0) { t = (double)(n >> 6); half = 16.0; }
    else           { t = (double)(n & 63); half = 32.0; }
    double inv_freq = pow(10000.0, -((double)(2*p)) / 32.0);
    double f  = t * inv_freq;
    double sbase = ((double)(2*p) + 0.4*32.0) / (1.4*32.0);
    double power = (t - half) / 64.0;
    double sc = pow(sbase, power);
    g_cos[idx] = (float)cos(f);
    g_sin[idx] = (float)sin(f);
    g_xs [idx] = (float)sc;
}

// ============================================================
// Kernel 2: TF32 GEMM, 128x128 tile, cp.async 2-stage, 8 warps
//   QKV=true : C = X*W+b, fused RoPE/xpos, scatter to g_qkv
//   QKV=false: C = g_att*W+b -> out
// ============================================================
#define AS_STR 36
#define BS_STR 136
#define GEMM_SMEM ((2*128*AS_STR + 2*32*BS_STR)*4)   // 71680 B

template<int NC, bool QKV>
__global__ __launch_bounds__(256, 2) void gemm_tf32_kernel(
    const float* __restrict__ X, const float* __restrict__ W,
    const float* __restrict__ bias, float* __restrict__ out)
{
    extern __shared__ float gsm[];
    float* As = gsm;                       // [2][128][AS_STR]
    float* Bs = gsm + 2*128*AS_STR;        // [2][32][BS_STR]

    const float* Xp = QKV ? X : (const float*)g_att;

    int tid = threadIdx.x;
    int lane = tid & 31, warp = tid >> 5;
    int lq = lane >> 2, lr = lane & 3;
    int wm = (warp >> 2) * 64;
    int wn = (warp & 3) * 32;
    int bm = blockIdx.y * 128, bn = blockIdx.x * 128;

    float acc[4][4][4];
#pragma unroll
    for (int mi = 0; mi < 4; mi++)
#pragma unroll
        for (int ni = 0; ni < 4; ni++)
#pragma unroll
            for (int r = 0; r < 4; r++) acc[mi][ni][r] = 0.f;

    int ar = tid >> 3, ac = (tid & 7) << 2;
    int br = tid >> 5, bc = (tid & 31) << 2;

    unsigned sA = (unsigned)__cvta_generic_to_shared(As);
    unsigned sB = (unsigned)__cvta_generic_to_shared(Bs);

    auto issue = [&](int stage, int k0) {
        unsigned dA = sA + (unsigned)(stage*128*AS_STR)*4;
        unsigned dB = sB + (unsigned)(stage*32*BS_STR)*4;
#pragma unroll
        for (int p = 0; p < 4; p++)
            cpa16(dA + (unsigned)((ar + p*32)*AS_STR + ac)*4,
                  Xp + (size_t)(bm + ar + p*32)*1024 + k0 + ac);
#pragma unroll
        for (int p = 0; p < 4; p++)
            cpa16(dB + (unsigned)((br + p*8)*BS_STR + bc)*4,
                  W + (size_t)(k0 + br + p*8)*NC + bn + bc);
        cpa_commit();
    };

    issue(0, 0);

    const int NIT = 1024/32;
    for (int it = 0; it < NIT; it++) {
        int cur = it & 1;
        cpa_wait<0>();
        __syncthreads();
        if (it + 1 < NIT) issue(cur ^ 1, (it+1)*32);

        const float* Af = As + cur*128*AS_STR;
        const float* Bf = Bs + cur*32*BS_STR;
#pragma unroll
        for (int kk = 0; kk < 4; kk++) {
            unsigned af[4][4], bf[4][2];
#pragma unroll
            for (int mi = 0; mi < 4; mi++) {
                int r = wm + mi*16 + lq, c = kk*8 + lr;
                af[mi][0] = f2tf(Af[r*AS_STR + c]);
                af[mi][1] = f2tf(Af[(r+8)*AS_STR + c]);
                af[mi][2] = f2tf(Af[r*AS_STR + c + 4]);
                af[mi][3] = f2tf(Af[(r+8)*AS_STR + c + 4]);
            }
#pragma unroll
            for (int ni = 0; ni < 4; ni++) {
                int c = wn + ni*8 + lq, r = kk*8 + lr;
                bf[ni][0] = f2tf(Bf[r*BS_STR + c]);
                bf[ni][1] = f2tf(Bf[(r+4)*BS_STR + c]);
            }
#pragma unroll
            for (int mi = 0; mi < 4; mi++)
#pragma unroll
                for (int ni = 0; ni < 4; ni++)
                    mma8(acc[mi][ni], af[mi], bf[ni][0], bf[ni][1]);
        }
        __syncthreads();
    }

    // ---- epilogue ----
#pragma unroll
    for (int mi = 0; mi < 4; mi++) {
#pragma unroll
        for (int ni = 0; ni < 4; ni++) {
            int col = bn + wn + ni*8 + 2*lr;
            float bz0 = bias[col], bz1 = bias[col+1];
            int rA = bm + wm + mi*16 + lq;
            int rB = rA + 8;
            float a0 = acc[mi][ni][0] + bz0, a1 = acc[mi][ni][1] + bz1;
            float b0 = acc[mi][ni][2] + bz0, b1 = acc[mi][ni][3] + bz1;
            if (QKV) {
                int which = col >> 10, hh = (col >> 6) & 15, dd = col & 63;
                int bA = rA >> 11, nA = rA & 2047;
                int bB = rB >> 11, nB = rB & 2047;
                if (which < 2) {   // rotate q,k; v passthrough
                    int tiA = (nA << 6) + dd, tiB = (nB << 6) + dd;
                    float cA = g_cos[tiA], sA_ = g_sin[tiA], xA = g_xs[tiA];
                    float cB = g_cos[tiB], sB_ = g_sin[tiB], xB = g_xs[tiB];
                    float y0 = a0*cA - a1*sA_, y1 = a1*cA + a0*sA_;
                    float z0 = b0*cB - b1*sB_, z1 = b1*cB + b0*sB_;
                    if (which == 0) { a0 = y0*xA; a1 = y1*xA; b0 = z0*xB; b1 = z1*xB; }
                    else            { a0 = y0/xA; a1 = y1/xA; b0 = z0/xB; b1 = z1/xB; }
                }
                *(float2*)&g_qkv[((size_t)(((which*2 + bA)*16 + hh))*2048 + nA)*64 + dd] = make_float2(a0, a1);
                *(float2*)&g_qkv[((size_t)(((which*2 + bB)*16 + hh))*2048 + nB)*64 + dd] = make_float2(b0, b1);
            } else {
                *(float2*)&out[(size_t)rA*NC + col] = make_float2(a0, a1);
                *(float2*)&out[(size_t)rB*NC + col] = make_float2(b0, b1);
            }
        }
    }
}

// ============================================================
// Kernel 3: flash attention, TF32 mma, vectorized frag LDS
//   grid (16, 32), 256 thr (8 warps), warp owns 16 q-rows.
//   Ks: [token][d-permuted]   — B-frag pair = one LDS.64
//   Vt: [d][token-permuted]   — B-frag pair = one LDS.64
//   Ps: [128][FSTR]           — Q staging, then P (unpermuted)
// ============================================================
#define FSTR 72
#define FLASH_SMEM (256*FSTR*4)   // Ks(64) + Vt(64) + Ps(128) rows

__global__ __launch_bounds__(256, 2) void flash_tf32_kernel() {
    extern __shared__ unsigned sm_u[];
    unsigned* Ks = sm_u;                 // [64][FSTR]
    unsigned* Vt = sm_u + 64*FSTR;       // [64][FSTR]
    unsigned* Ps = sm_u + 128*FSTR;      // [128][FSTR]

    int tid = threadIdx.x;
    int lane = tid & 31, warp = tid >> 5;
    int lq = lane >> 2, lr = lane & 3;
    int qt = blockIdx.x, bh = blockIdx.y;
    int b = bh >> 4, h = bh & 15;
    int r0 = warp * 16;

    const float* Qg = g_qkv + ((size_t)((0*BATCH + b)*NHEADS + h))*NTOK*HDIM + (size_t)qt*128*HDIM;
    const float* Kg = g_qkv + ((size_t)((1*BATCH + b)*NHEADS + h))*NTOK*HDIM;
    const float* Vg = g_qkv + ((size_t)((2*BATCH + b)*NHEADS + h))*NTOK*HDIM;

    // stage Q (scaled 1/8, tf32) into Ps, load frags
    {
        int r = tid >> 4, c4 = (tid & 15) << 2;
#pragma unroll
        for (int p = 0; p < 8; p++) {
            float4 v = *(const float4*)(Qg + (size_t)(r + p*16)*HDIM + c4);
            unsigned* d = &Ps[(r + p*16)*FSTR + c4];
            d[0] = f2tf(v.x*0.125f); d[1] = f2tf(v.y*0.125f);
            d[2] = f2tf(v.z*0.125f); d[3] = f2tf(v.w*0.125f);
        }
    }
    __syncthreads();

    unsigned qf[8][4];
#pragma unroll
    for (int kk = 0; kk < 8; kk++) {
        int c = kk*8 + lr;
        qf[kk][0] = Ps[(r0 + lq)*FSTR + c];
        qf[kk][1] = Ps[(r0 + lq + 8)*FSTR + c];
        qf[kk][2] = Ps[(r0 + lq)*FSTR + c + 4];
        qf[kk][3] = Ps[(r0 + lq + 8)*FSTR + c + 4];
    }

    float O[8][4];
    float mstate[2] = {-1e30f, -1e30f};
    float lstate[2] = {0.f, 0.f};
#pragma unroll
    for (int n = 0; n < 8; n++)
#pragma unroll
        for (int r = 0; r < 4; r++) O[n][r] = 0.f;

    for (int kt = 0; kt < NTOK/64; kt++) {
        __syncthreads();   // WAR on Ks/Vt/Ps
        {
            int r = tid >> 4, c4 = (tid & 15) << 2;
            int pb = c4 & ~7;                 // permuted col base for K
            int x  = (c4 >> 2) & 1;
            const float* kg = Kg + (size_t)kt*64*HDIM;
            const float* vg = Vg + (size_t)kt*64*HDIM;
#pragma unroll
            for (int p = 0; p < 4; p++) {
                int t = r + p*16;
                float4 kv = *(const float4*)(kg + (size_t)t*HDIM + c4);
                unsigned* dk = &Ks[t*FSTR + pb + x];
                dk[0]=f2tf(kv.x); dk[2]=f2tf(kv.y); dk[4]=f2tf(kv.z); dk[6]=f2tf(kv.w);
                float4 vv = *(const float4*)(vg + (size_t)t*HDIM + c4);
                int tp = (t & ~7) | ((t & 3) << 1) | ((t >> 2) & 1);  // permuted token
                Vt[(c4+0)*FSTR + tp] = f2tf(vv.x);
                Vt[(c4+1)*FSTR + tp] = f2tf(vv.y);
                Vt[(c4+2)*FSTR + tp] = f2tf(vv.z);
                Vt[(c4+3)*FSTR + tp] = f2tf(vv.w);
            }
        }
        __syncthreads();

        // ---- S = Q K^T ----
        float s[8][4];
#pragma unroll
        for (int n = 0; n < 8; n++) {
            s[n][0] = s[n][1] = s[n][2] = s[n][3] = 0.f;
            const unsigned* krow = &Ks[(n*8 + lq)*FSTR + 2*lr];
#pragma unroll
            for (int kk = 0; kk < 8; kk++) {
                uint2 kb = *(const uint2*)(krow + kk*8);
                mma8(s[n], qf[kk], kb.x, kb.y);
            }
        }

        // ---- online softmax ----
        float mA = -1e30f, mB = -1e30f;
#pragma unroll
        for (int n = 0; n < 8; n++) {
            mA = fmaxf(mA, fmaxf(s[n][0], s[n][1]));
            mB = fmaxf(mB, fmaxf(s[n][2], s[n][3]));
        }
        mA = fmaxf(mA, __shfl_xor_sync(0xffffffffu, mA, 1));
        mA = fmaxf(mA, __shfl_xor_sync(0xffffffffu, mA, 2));
        mB = fmaxf(mB, __shfl_xor_sync(0xffffffffu, mB, 1));
        mB = fmaxf(mB, __shfl_xor_sync(0xffffffffu, mB, 2));
        float mnA = fmaxf(mstate[0], mA), mnB = fmaxf(mstate[1], mB);
        float corrA = __expf(mstate[0] - mnA), corrB = __expf(mstate[1] - mnB);
        float sumA = 0.f, sumB = 0.f;
#pragma unroll
        for (int n = 0; n < 8; n++) {
            float p0 = __expf(s[n][0] - mnA), p1 = __expf(s[n][1] - mnA);
            float p2 = __expf(s[n][2] - mnB), p3 = __expf(s[n][3] - mnB);
            sumA += p0 + p1; sumB += p2 + p3;
            uint2 uA; uA.x = f2tf(p0); uA.y = f2tf(p1);
            uint2 uB; uB.x = f2tf(p2); uB.y = f2tf(p3);
            *(uint2*)&Ps[(r0 + lq)*FSTR + n*8 + 2*lr]     = uA;
            *(uint2*)&Ps[(r0 + lq + 8)*FSTR + n*8 + 2*lr] = uB;
        }
        sumA += __shfl_xor_sync(0xffffffffu, sumA, 1);
        sumA += __shfl_xor_sync(0xffffffffu, sumA, 2);
        sumB += __shfl_xor_sync(0xffffffffu, sumB, 1);
        sumB += __shfl_xor_sync(0xffffffffu, sumB, 2);
        lstate[0] = lstate[0]*corrA + sumA; mstate[0] = mnA;
        lstate[1] = lstate[1]*corrB + sumB; mstate[1] = mnB;
#pragma unroll
        for (int n = 0; n < 8; n++) {
            O[n][0] *= corrA; O[n][1] *= corrA;
            O[n][2] *= corrB; O[n][3] *= corrB;
        }
        __syncwarp();

        // ---- O += P V ----
#pragma unroll
        for (int kk = 0; kk < 8; kk++) {
            unsigned pa[4];
            int c = kk*8 + lr;
            pa[0] = Ps[(r0 + lq)*FSTR + c];
            pa[1] = Ps[(r0 + lq + 8)*FSTR + c];
            pa[2] = Ps[(r0 + lq)*FSTR + c + 4];
            pa[3] = Ps[(r0 + lq + 8)*FSTR + c + 4];
            const unsigned* vrow = &Vt[0] + kk*8 + 2*lr;
#pragma unroll
            for (int n = 0; n < 8; n++) {
                uint2 vb = *(const uint2*)(vrow + (n*8 + lq)*FSTR);
                mma8(O[n], pa, vb.x, vb.y);
            }
        }
    }

    // epilogue: normalize, write [B][N][H*D]
    float invA = 1.f / lstate[0], invB = 1.f / lstate[1];
    int rowA = qt*128 + r0 + lq;
    int rowB = rowA + 8;
#pragma unroll
    for (int n = 0; n < 8; n++) {
        int col = h*HDIM + n*8 + 2*lr;
        *(float2*)&g_att[(size_t)(b*NTOK + rowA)*D_MODEL + col] = make_float2(O[n][0]*invA, O[n][1]*invA);
        *(float2*)&g_att[(size_t)(b*NTOK + rowB)*D_MODEL + col] = make_float2(O[n][2]*invB, O[n][3]*invB);
    }
}

// ============================================================
// launch
// ============================================================
extern "C" void kernel_launch(void* const* d_in, const int* in_sizes, int n_in,
                              void* d_out, int out_size) {
    const float* x      = (const float*)d_in[0];
    const float* w_qkv  = (const float*)d_in[1];
    const float* b_qkv  = (const float*)d_in[2];
    const float* w_proj = (const float*)d_in[3];
    const float* b_proj = (const float*)d_in[4];
    float* out = (float*)d_out;
    (void)in_sizes; (void)n_in; (void)out_size;

    rope_tables_kernel<<<(NTOK*HDIM)/256, 256>>>();

    cudaFuncSetAttribute(gemm_tf32_kernel<QKVCOLS, true>,
                         cudaFuncAttributeMaxDynamicSharedMemorySize, GEMM_SMEM);
    gemm_tf32_kernel<QKVCOLS, true><<<dim3(QKVCOLS/128, MROWS/128), 256, GEMM_SMEM>>>(x, w_qkv, b_qkv, nullptr);

    cudaFuncSetAttribute(flash_tf32_kernel,
                         cudaFuncAttributeMaxDynamicSharedMemorySize, FLASH_SMEM);
    flash_tf32_kernel<<<dim3(NTOK/128, BATCH*NHEADS), 256, FLASH_SMEM>>>();

    cudaFuncSetAttribute(gemm_tf32_kernel<D_MODEL, false>,
                         cudaFuncAttributeMaxDynamicSharedMemorySize, GEMM_SMEM);
    gemm_tf32_kernel<D_MODEL, false><<<dim3(D_MODEL/128, MROWS/128), 256, GEMM_SMEM>>>(nullptr, w_proj, b_proj, out);
}

// round 4
// speedup vs baseline: 1.1775x; 1.1775x over previous
#include <cuda_runtime.h>
#include <math.h>

// ---------------- problem constants ----------------
#define D_MODEL  1024
#define NHEADS   16
#define HDIM     64
#define NTOK     2048
#define BATCH    2
#define MROWS    (BATCH*NTOK)       // 4096
#define QKVCOLS  (3*D_MODEL)        // 3072

// ---------------- scratch ----------------
__device__ float g_qkv[3*BATCH*NHEADS*NTOK*HDIM]; // [which][B][H][N][D]
__device__ float g_att[MROWS*D_MODEL];            // [B*N][H*D]
__device__ float g_cos[NTOK*HDIM];
__device__ float g_sin[NTOK*HDIM];
__device__ float g_xs [NTOK*HDIM];

// ---------------- helpers ----------------
__device__ __forceinline__ unsigned f2tf(float f) {
    unsigned u;
    asm("cvt.rna.tf32.f32 %0, %1;" : "=r"(u) : "f"(f));
    return u;
}
__device__ __forceinline__ void mma8(float c[4], const unsigned a[4], unsigned b0, unsigned b1) {
    asm("mma.sync.aligned.m16n8k8.row.col.f32.tf32.tf32.f32 "
        "{%0,%1,%2,%3},{%4,%5,%6,%7},{%8,%9},{%0,%1,%2,%3};"
        : "+f"(c[0]), "+f"(c[1]), "+f"(c[2]), "+f"(c[3])
        : "r"(a[0]), "r"(a[1]), "r"(a[2]), "r"(a[3]), "r"(b0), "r"(b1));
}
__device__ __forceinline__ void cpa16(unsigned dst, const void* src) {
    asm volatile("cp.async.cg.shared.global [%0], [%1], 16;" :: "r"(dst), "l"(src));
}
__device__ __forceinline__ void cpa_commit() {
    asm volatile("cp.async.commit_group;");
}
template<int N>
__device__ __forceinline__ void cpa_wait() {
    asm volatile("cp.async.wait_group %0;" :: "n"(N));
}

// ============================================================
// Kernel 1: xpos/ND-RoPE tables (fp64, matches numpy ref)
// ============================================================
__global__ void rope_tables_kernel() {
    int idx = blockIdx.x * blockDim.x + threadIdx.x;
    if (idx >= NTOK*HDIM) return;
    int n = idx >> 6;
    int d = idx & 63;
    int axis = d >> 5;
    int jj   = d & 31;
    int p    = jj >> 1;
    double t, half;
    if (axis == 0) { t = (double)(n >> 6); half = 16.0; }
    else           { t = (double)(n & 63); half = 32.0; }
    double inv_freq = pow(10000.0, -((double)(2*p)) / 32.0);
    double f  = t * inv_freq;
    double sbase = ((double)(2*p) + 0.4*32.0) / (1.4*32.0);
    double power = (t - half) / 64.0;
    double sc = pow(sbase, power);
    g_cos[idx] = (float)cos(f);
    g_sin[idx] = (float)sin(f);
    g_xs [idx] = (float)sc;
}

// ============================================================
// Kernel 2: TF32 GEMM, TMx128 tile, true 2-stage cp.async
//   QKV=true : C = X*W+b, fused RoPE/xpos, scatter to g_qkv
//   QKV=false: C = g_att*W+b -> out
// ============================================================
#define AS_STR 36
#define BS_STR 136
#define GEMM_SMEM(TM) ((2*(TM)*AS_STR + 2*32*BS_STR)*4)

template<int NC, bool QKV, int TM>
__global__ __launch_bounds__(256, 2) void gemm_tf32_kernel(
    const float* __restrict__ X, const float* __restrict__ W,
    const float* __restrict__ bias, float* __restrict__ out)
{
    constexpr int MI = TM/32;           // warp m-subtiles & A-load passes
    extern __shared__ float gsm[];
    float* As = gsm;                       // [2][TM][AS_STR]
    float* Bs = gsm + 2*TM*AS_STR;         // [2][32][BS_STR]

    const float* Xp = QKV ? X : (const float*)g_att;

    int tid = threadIdx.x;
    int lane = tid & 31, warp = tid >> 5;
    int lq = lane >> 2, lr = lane & 3;
    int wm = (warp >> 2) * (TM/2);
    int wn = (warp & 3) * 32;
    int bm = blockIdx.y * TM, bn = blockIdx.x * 128;

    float acc[MI][4][4];
#pragma unroll
    for (int mi = 0; mi < MI; mi++)
#pragma unroll
        for (int ni = 0; ni < 4; ni++)
#pragma unroll
            for (int r = 0; r < 4; r++) acc[mi][ni][r] = 0.f;

    int ar = tid >> 3, ac = (tid & 7) << 2;   // A: MI passes of 32 rows
    int br = tid >> 5, bc = (tid & 31) << 2;  // B: 4 passes of 8 k-rows

    unsigned sA = (unsigned)__cvta_generic_to_shared(As);
    unsigned sB = (unsigned)__cvta_generic_to_shared(Bs);

    auto issue = [&](int stage, int k0) {
        unsigned dA = sA + (unsigned)(stage*TM*AS_STR)*4;
        unsigned dB = sB + (unsigned)(stage*32*BS_STR)*4;
#pragma unroll
        for (int p = 0; p < MI; p++)
            cpa16(dA + (unsigned)((ar + p*32)*AS_STR + ac)*4,
                  Xp + (size_t)(bm + ar + p*32)*1024 + k0 + ac);
#pragma unroll
        for (int p = 0; p < 4; p++)
            cpa16(dB + (unsigned)((br + p*8)*BS_STR + bc)*4,
                  W + (size_t)(k0 + br + p*8)*NC + bn + bc);
        cpa_commit();
    };

    issue(0, 0);
    issue(1, 32);

    const int NIT = 1024/32;
    for (int it = 0; it < NIT; it++) {
        int cur = it & 1;
        if (it + 2 < NIT) cpa_wait<1>(); else cpa_wait<0>();
        __syncthreads();

        const float* Af = As + cur*TM*AS_STR;
        const float* Bf = Bs + cur*32*BS_STR;
#pragma unroll
        for (int kk = 0; kk < 4; kk++) {
            unsigned af[MI][4], bf[4][2];
#pragma unroll
            for (int mi = 0; mi < MI; mi++) {
                int r = wm + mi*16 + lq, c = kk*8 + lr;
                af[mi][0] = f2tf(Af[r*AS_STR + c]);
                af[mi][1] = f2tf(Af[(r+8)*AS_STR + c]);
                af[mi][2] = f2tf(Af[r*AS_STR + c + 4]);
                af[mi][3] = f2tf(Af[(r+8)*AS_STR + c + 4]);
            }
#pragma unroll
            for (int ni = 0; ni < 4; ni++) {
                int c = wn + ni*8 + lq, r = kk*8 + lr;
                bf[ni][0] = f2tf(Bf[r*BS_STR + c]);
                bf[ni][1] = f2tf(Bf[(r+4)*BS_STR + c]);
            }
#pragma unroll
            for (int mi = 0; mi < MI; mi++)
#pragma unroll
                for (int ni = 0; ni < 4; ni++)
                    mma8(acc[mi][ni], af[mi], bf[ni][0], bf[ni][1]);
        }
        __syncthreads();
        if (it + 2 < NIT) issue(cur, (it+2)*32);
    }

    // ---- epilogue ----
#pragma unroll
    for (int mi = 0; mi < MI; mi++) {
#pragma unroll
        for (int ni = 0; ni < 4; ni++) {
            int col = bn + wn + ni*8 + 2*lr;
            float bz0 = bias[col], bz1 = bias[col+1];
            int rA = bm + wm + mi*16 + lq;
            int rB = rA + 8;
            float a0 = acc[mi][ni][0] + bz0, a1 = acc[mi][ni][1] + bz1;
            float b0 = acc[mi][ni][2] + bz0, b1 = acc[mi][ni][3] + bz1;
            if (QKV) {
                int which = col >> 10, hh = (col >> 6) & 15, dd = col & 63;
                int bA = rA >> 11, nA = rA & 2047;
                int bB = rB >> 11, nB = rB & 2047;
                if (which < 2) {   // rotate q,k; v passthrough
                    int tiA = (nA << 6) + dd, tiB = (nB << 6) + dd;
                    float cA = g_cos[tiA], sA_ = g_sin[tiA], xA = g_xs[tiA];
                    float cB = g_cos[tiB], sB_ = g_sin[tiB], xB = g_xs[tiB];
                    float y0 = a0*cA - a1*sA_, y1 = a1*cA + a0*sA_;
                    float z0 = b0*cB - b1*sB_, z1 = b1*cB + b0*sB_;
                    if (which == 0) { a0 = y0*xA; a1 = y1*xA; b0 = z0*xB; b1 = z1*xB; }
                    else            { a0 = y0/xA; a1 = y1/xA; b0 = z0/xB; b1 = z1/xB; }
                }
                *(float2*)&g_qkv[((size_t)(((which*2 + bA)*16 + hh))*2048 + nA)*64 + dd] = make_float2(a0, a1);
                *(float2*)&g_qkv[((size_t)(((which*2 + bB)*16 + hh))*2048 + nB)*64 + dd] = make_float2(b0, b1);
            } else {
                *(float2*)&out[(size_t)rA*NC + col] = make_float2(a0, a1);
                *(float2*)&out[(size_t)rB*NC + col] = make_float2(b0, b1);
            }
        }
    }
}

// ============================================================
// Kernel 3: flash attention, TF32 mma
//   Ks: [token][d-permuted] — B-frag pair = one LDS.64
//   Vs: [token][d]          — scalar B-frag LDS, conflict-free
//   Ps: [128][FSTR]         — Q staging, then P
// ============================================================
#define FSTR 72
#define FLASH_SMEM (256*FSTR*4)

__global__ __launch_bounds__(256, 2) void flash_tf32_kernel() {
    extern __shared__ unsigned sm_u[];
    unsigned* Ks = sm_u;                 // [64][FSTR]
    unsigned* Vs = sm_u + 64*FSTR;       // [64][FSTR]
    unsigned* Ps = sm_u + 128*FSTR;      // [128][FSTR]

    int tid = threadIdx.x;
    int lane = tid & 31, warp = tid >> 5;
    int lq = lane >> 2, lr = lane & 3;
    int qt = blockIdx.x, bh = blockIdx.y;
    int b = bh >> 4, h = bh & 15;
    int r0 = warp * 16;

    const float* Qg = g_qkv + ((size_t)((0*BATCH + b)*NHEADS + h))*NTOK*HDIM + (size_t)qt*128*HDIM;
    const float* Kg = g_qkv + ((size_t)((1*BATCH + b)*NHEADS + h))*NTOK*HDIM;
    const float* Vg = g_qkv + ((size_t)((2*BATCH + b)*NHEADS + h))*NTOK*HDIM;

    // stage Q (scaled 1/8, tf32) into Ps, load frags
    {
        int r = tid >> 4, c4 = (tid & 15) << 2;
#pragma unroll
        for (int p = 0; p < 8; p++) {
            float4 v = *(const float4*)(Qg + (size_t)(r + p*16)*HDIM + c4);
            unsigned* d = &Ps[(r + p*16)*FSTR + c4];
            d[0] = f2tf(v.x*0.125f); d[1] = f2tf(v.y*0.125f);
            d[2] = f2tf(v.z*0.125f); d[3] = f2tf(v.w*0.125f);
        }
    }
    __syncthreads();

    unsigned qf[8][4];
#pragma unroll
    for (int kk = 0; kk < 8; kk++) {
        int c = kk*8 + lr;
        qf[kk][0] = Ps[(r0 + lq)*FSTR + c];
        qf[kk][1] = Ps[(r0 + lq + 8)*FSTR + c];
        qf[kk][2] = Ps[(r0 + lq)*FSTR + c + 4];
        qf[kk][3] = Ps[(r0 + lq + 8)*FSTR + c + 4];
    }

    float O[8][4];
    float mstate[2] = {-1e30f, -1e30f};
    float lstate[2] = {0.f, 0.f};
#pragma unroll
    for (int n = 0; n < 8; n++)
#pragma unroll
        for (int r = 0; r < 4; r++) O[n][r] = 0.f;

    for (int kt = 0; kt < NTOK/64; kt++) {
        __syncthreads();   // WAR on Ks/Vs/Ps
        {
            int r = tid >> 4, c4 = (tid & 15) << 2;
            int pb = c4 & ~7;                 // permuted col base for K
            int x  = (c4 >> 2) & 1;
            const float* kg = Kg + (size_t)kt*64*HDIM;
            const float* vg = Vg + (size_t)kt*64*HDIM;
#pragma unroll
            for (int p = 0; p < 4; p++) {
                int t = r + p*16;
                float4 kv = *(const float4*)(kg + (size_t)t*HDIM + c4);
                unsigned* dk = &Ks[t*FSTR + pb + x];
                dk[0]=f2tf(kv.x); dk[2]=f2tf(kv.y); dk[4]=f2tf(kv.z); dk[6]=f2tf(kv.w);
                float4 vv = *(const float4*)(vg + (size_t)t*HDIM + c4);
                unsigned* dv = &Vs[t*FSTR + c4];
                dv[0]=f2tf(vv.x); dv[1]=f2tf(vv.y); dv[2]=f2tf(vv.z); dv[3]=f2tf(vv.w);
            }
        }
        __syncthreads();

        // ---- S = Q K^T ----
        float s[8][4];
#pragma unroll
        for (int n = 0; n < 8; n++) {
            s[n][0] = s[n][1] = s[n][2] = s[n][3] = 0.f;
            const unsigned* krow = &Ks[(n*8 + lq)*FSTR + 2*lr];
#pragma unroll
            for (int kk = 0; kk < 8; kk++) {
                uint2 kb = *(const uint2*)(krow + kk*8);
                mma8(s[n], qf[kk], kb.x, kb.y);
            }
        }

        // ---- online softmax ----
        float mA = -1e30f, mB = -1e30f;
#pragma unroll
        for (int n = 0; n < 8; n++) {
            mA = fmaxf(mA, fmaxf(s[n][0], s[n][1]));
            mB = fmaxf(mB, fmaxf(s[n][2], s[n][3]));
        }
        mA = fmaxf(mA, __shfl_xor_sync(0xffffffffu, mA, 1));
        mA = fmaxf(mA, __shfl_xor_sync(0xffffffffu, mA, 2));
        mB = fmaxf(mB, __shfl_xor_sync(0xffffffffu, mB, 1));
        mB = fmaxf(mB, __shfl_xor_sync(0xffffffffu, mB, 2));
        float mnA = fmaxf(mstate[0], mA), mnB = fmaxf(mstate[1], mB);
        float corrA = __expf(mstate[0] - mnA), corrB = __expf(mstate[1] - mnB);
        float sumA = 0.f, sumB = 0.f;
#pragma unroll
        for (int n = 0; n < 8; n++) {
            float p0 = __expf(s[n][0] - mnA), p1 = __expf(s[n][1] - mnA);
            float p2 = __expf(s[n][2] - mnB), p3 = __expf(s[n][3] - mnB);
            sumA += p0 + p1; sumB += p2 + p3;
            uint2 uA; uA.x = f2tf(p0); uA.y = f2tf(p1);
            uint2 uB; uB.x = f2tf(p2); uB.y = f2tf(p3);
            *(uint2*)&Ps[(r0 + lq)*FSTR + n*8 + 2*lr]     = uA;
            *(uint2*)&Ps[(r0 + lq + 8)*FSTR + n*8 + 2*lr] = uB;
        }
        sumA += __shfl_xor_sync(0xffffffffu, sumA, 1);
        sumA += __shfl_xor_sync(0xffffffffu, sumA, 2);
        sumB += __shfl_xor_sync(0xffffffffu, sumB, 1);
        sumB += __shfl_xor_sync(0xffffffffu, sumB, 2);
        lstate[0] = lstate[0]*corrA + sumA; mstate[0] = mnA;
        lstate[1] = lstate[1]*corrB + sumB; mstate[1] = mnB;
#pragma unroll
        for (int n = 0; n < 8; n++) {
            O[n][0] *= corrA; O[n][1] *= corrA;
            O[n][2] *= corrB; O[n][3] *= corrB;
        }
        __syncwarp();

        // ---- O += P V ----
#pragma unroll
        for (int kk = 0; kk < 8; kk++) {
            unsigned pa[4];
            int c = kk*8 + lr;
            pa[0] = Ps[(r0 + lq)*FSTR + c];
            pa[1] = Ps[(r0 + lq + 8)*FSTR + c];
            pa[2] = Ps[(r0 + lq)*FSTR + c + 4];
            pa[3] = Ps[(r0 + lq + 8)*FSTR + c + 4];
#pragma unroll
            for (int n = 0; n < 8; n++) {
                unsigned vb0 = Vs[(kk*8 + lr)*FSTR + n*8 + lq];
                unsigned vb1 = Vs[(kk*8 + lr + 4)*FSTR + n*8 + lq];
                mma8(O[n], pa, vb0, vb1);
            }
        }
    }

    // epilogue: normalize, write [B][N][H*D]
    float invA = 1.f / lstate[0], invB = 1.f / lstate[1];
    int rowA = qt*128 + r0 + lq;
    int rowB = rowA + 8;
#pragma unroll
    for (int n = 0; n < 8; n++) {
        int col = h*HDIM + n*8 + 2*lr;
        *(float2*)&g_att[(size_t)(b*NTOK + rowA)*D_MODEL + col] = make_float2(O[n][0]*invA, O[n][1]*invA);
        *(float2*)&g_att[(size_t)(b*NTOK + rowB)*D_MODEL + col] = make_float2(O[n][2]*invB, O[n][3]*invB);
    }
}

// ============================================================
// launch
// ============================================================
extern "C" void kernel_launch(void* const* d_in, const int* in_sizes, int n_in,
                              void* d_out, int out_size) {
    const float* x      = (const float*)d_in[0];
    const float* w_qkv  = (const float*)d_in[1];
    const float* b_qkv  = (const float*)d_in[2];
    const float* w_proj = (const float*)d_in[3];
    const float* b_proj = (const float*)d_in[4];
    float* out = (float*)d_out;
    (void)in_sizes; (void)n_in; (void)out_size;

    rope_tables_kernel<<<(NTOK*HDIM)/256, 256>>>();

    cudaFuncSetAttribute(gemm_tf32_kernel<QKVCOLS, true, 128>,
                         cudaFuncAttributeMaxDynamicSharedMemorySize, GEMM_SMEM(128));
    gemm_tf32_kernel<QKVCOLS, true, 128>
        <<<dim3(QKVCOLS/128, MROWS/128), 256, GEMM_SMEM(128)>>>(x, w_qkv, b_qkv, nullptr);

    cudaFuncSetAttribute(flash_tf32_kernel,
                         cudaFuncAttributeMaxDynamicSharedMemorySize, FLASH_SMEM);
    flash_tf32_kernel<<<dim3(NTOK/128, BATCH*NHEADS), 256, FLASH_SMEM>>>();

    cudaFuncSetAttribute(gemm_tf32_kernel<D_MODEL, false, 64>,
                         cudaFuncAttributeMaxDynamicSharedMemorySize, GEMM_SMEM(64));
    gemm_tf32_kernel<D_MODEL, false, 64>
        <<<dim3(D_MODEL/128, MROWS/64), 256, GEMM_SMEM(64)>>>(nullptr, w_proj, b_proj, out);
}

// round 5
// speedup vs baseline: 1.2413x; 1.0542x over previous
#include <cuda_runtime.h>
#include <math.h>

// ---------------- problem constants ----------------
#define D_MODEL  1024
#define NHEADS   16
#define HDIM     64
#define NTOK     2048
#define BATCH    2
#define MROWS    (BATCH*NTOK)       // 4096
#define QKVCOLS  (3*D_MODEL)        // 3072

// ---------------- scratch (tf32 bit patterns stored as unsigned) ----------------
__device__ unsigned g_qkv[3*BATCH*NHEADS*NTOK*HDIM]; // [which][B][H][N][D] (Q,K col-permuted; Q pre-scaled)
__device__ unsigned g_att[MROWS*D_MODEL];            // [B*N][H*D] col-permuted tf32
__device__ unsigned g_xt [MROWS*D_MODEL];            // X, tf32, col-permuted
__device__ unsigned g_wq [D_MODEL*QKVCOLS];          // w_qkv, tf32
__device__ unsigned g_wp [D_MODEL*D_MODEL];          // w_proj, tf32
__device__ float g_cos[NTOK*HDIM];
__device__ float g_sin[NTOK*HDIM];
__device__ float g_xs [NTOK*HDIM];

// ---------------- helpers ----------------
__device__ __forceinline__ unsigned f2tf(float f) {
    unsigned u;
    asm("cvt.rna.tf32.f32 %0, %1;" : "=r"(u) : "f"(f));
    return u;
}
__device__ __forceinline__ void mma8(float c[4], const unsigned a[4], unsigned b0, unsigned b1) {
    asm("mma.sync.aligned.m16n8k8.row.col.f32.tf32.tf32.f32 "
        "{%0,%1,%2,%3},{%4,%5,%6,%7},{%8,%9},{%0,%1,%2,%3};"
        : "+f"(c[0]), "+f"(c[1]), "+f"(c[2]), "+f"(c[3])
        : "r"(a[0]), "r"(a[1]), "r"(a[2]), "r"(a[3]), "r"(b0), "r"(b1));
}
__device__ __forceinline__ void cpa16(unsigned dst, const void* src) {
    asm volatile("cp.async.cg.shared.global [%0], [%1], 16;" :: "r"(dst), "l"(src));
}
__device__ __forceinline__ void cpa_commit() {
    asm volatile("cp.async.commit_group;");
}
template<int N>
__device__ __forceinline__ void cpa_wait() {
    asm volatile("cp.async.wait_group %0;" :: "n"(N));
}

// ============================================================
// Kernel 1: xpos/ND-RoPE tables (fp64, matches numpy ref)
// ============================================================
__global__ void rope_tables_kernel() {
    int idx = blockIdx.x * blockDim.x + threadIdx.x;
    if (idx >= NTOK*HDIM) return;
    int n = idx >> 6;
    int d = idx & 63;
    int axis = d >> 5;
    int jj   = d & 31;
    int p    = jj >> 1;
    double t, half;
    if (axis == 0) { t = (double)(n >> 6); half = 16.0; }
    else           { t = (double)(n & 63); half = 32.0; }
    double inv_freq = pow(10000.0, -((double)(2*p)) / 32.0);
    double f  = t * inv_freq;
    double sbase = ((double)(2*p) + 0.4*32.0) / (1.4*32.0);
    double power = (t - half) / 64.0;
    double sc = pow(sbase, power);
    g_cos[idx] = (float)cos(f);
    g_sin[idx] = (float)sin(f);
    g_xs [idx] = (float)sc;
}

// ============================================================
// Kernel 1b: pre-convert X (permuted), w_qkv, w_proj to tf32 bits
//   perm within 8-block: logical k -> 2*(k&3) + ((k&4)>>2)
// ============================================================
__global__ void preconvert_kernel(const float* __restrict__ X,
                                  const float* __restrict__ Wq,
                                  const float* __restrict__ Wp) {
    const int NX  = MROWS*D_MODEL/4;
    const int NWQ = D_MODEL*QKVCOLS/4;
    const int NWP = D_MODEL*D_MODEL/4;
    int i = blockIdx.x * blockDim.x + threadIdx.x;
    if (i < NX) {
        float4 v = ((const float4*)X)[i];
        int e = i << 2;                        // element index (k 4-aligned)
        int off = (e & ~7) + ((e & 4) >> 2);   // permuted base
        g_xt[off+0] = f2tf(v.x);
        g_xt[off+2] = f2tf(v.y);
        g_xt[off+4] = f2tf(v.z);
        g_xt[off+6] = f2tf(v.w);
    } else if (i < NX + NWQ) {
        int j = i - NX;
        float4 v = ((const float4*)Wq)[j];
        uint4 u; u.x=f2tf(v.x); u.y=f2tf(v.y); u.z=f2tf(v.z); u.w=f2tf(v.w);
        ((uint4*)g_wq)[j] = u;
    } else {
        int j = i - NX - NWQ;
        if (j < NWP) {
            float4 v = ((const float4*)Wp)[j];
            uint4 u; u.x=f2tf(v.x); u.y=f2tf(v.y); u.z=f2tf(v.z); u.w=f2tf(v.w);
            ((uint4*)g_wp)[j] = u;
        }
    }
}

// ============================================================
// Kernel 2: TF32 GEMM, TMx128 tile, 2-stage cp.async, no cvt
//   A pre-converted+permuted, B pre-converted.
//   QKV=true : +bias, fused RoPE/xpos, Q pre-scale, scatter g_qkv
//   QKV=false: +bias -> out (fp32)
// ============================================================
#define AS_STR 40
#define BS_STR 136
#define GEMM_SMEM(TM) ((2*(TM)*AS_STR + 2*32*BS_STR)*4)

template<int NC, bool QKV, int TM>
__global__ __launch_bounds__(256, 2) void gemm_tf32_kernel(
    const float* __restrict__ bias, float* __restrict__ out)
{
    constexpr int MI = TM/32;
    extern __shared__ unsigned gsm_u[];
    unsigned* As = gsm_u;                    // [2][TM][AS_STR]
    unsigned* Bs = gsm_u + 2*TM*AS_STR;      // [2][32][BS_STR]

    const unsigned* Ap = QKV ? g_xt : g_att;
    const unsigned* Bp = QKV ? g_wq : g_wp;

    int tid = threadIdx.x;
    int lane = tid & 31, warp = tid >> 5;
    int lq = lane >> 2, lr = lane & 3;
    int wm = (warp >> 2) * (TM/2);
    int wn = (warp & 3) * 32;
    int bm = blockIdx.y * TM, bn = blockIdx.x * 128;

    float acc[MI][4][4];
#pragma unroll
    for (int mi = 0; mi < MI; mi++)
#pragma unroll
        for (int ni = 0; ni < 4; ni++)
#pragma unroll
            for (int r = 0; r < 4; r++) acc[mi][ni][r] = 0.f;

    int ar = tid >> 3, ac = (tid & 7) << 2;
    int br = tid >> 5, bc = (tid & 31) << 2;

    unsigned sA = (unsigned)__cvta_generic_to_shared(As);
    unsigned sB = (unsigned)__cvta_generic_to_shared(Bs);

    auto issue = [&](int stage, int k0) {
        unsigned dA = sA + (unsigned)(stage*TM*AS_STR)*4;
        unsigned dB = sB + (unsigned)(stage*32*BS_STR)*4;
#pragma unroll
        for (int p = 0; p < MI; p++)
            cpa16(dA + (unsigned)((ar + p*32)*AS_STR + ac)*4,
                  Ap + (size_t)(bm + ar + p*32)*1024 + k0 + ac);
#pragma unroll
        for (int p = 0; p < 4; p++)
            cpa16(dB + (unsigned)((br + p*8)*BS_STR + bc)*4,
                  Bp + (size_t)(k0 + br + p*8)*NC + bn + bc);
        cpa_commit();
    };

    issue(0, 0);
    issue(1, 32);

    const int NIT = 1024/32;
    for (int it = 0; it < NIT; it++) {
        int cur = it & 1;
        if (it + 2 < NIT) cpa_wait<1>(); else cpa_wait<0>();
        __syncthreads();

        const unsigned* Af = As + cur*TM*AS_STR;
        const unsigned* Bf = Bs + cur*32*BS_STR;
#pragma unroll
        for (int kk = 0; kk < 4; kk++) {
            unsigned af[MI][4], bf[4][2];
#pragma unroll
            for (int mi = 0; mi < MI; mi++) {
                int r = wm + mi*16 + lq;
                uint2 u0 = *(const uint2*)&Af[r*AS_STR + kk*8 + 2*lr];
                uint2 u1 = *(const uint2*)&Af[(r+8)*AS_STR + kk*8 + 2*lr];
                af[mi][0] = u0.x; af[mi][1] = u1.x;
                af[mi][2] = u0.y; af[mi][3] = u1.y;
            }
#pragma unroll
            for (int ni = 0; ni < 4; ni++) {
                int c = wn + ni*8 + lq;
                bf[ni][0] = Bf[(kk*8 + lr)*BS_STR + c];
                bf[ni][1] = Bf[(kk*8 + lr + 4)*BS_STR + c];
            }
#pragma unroll
            for (int mi = 0; mi < MI; mi++)
#pragma unroll
                for (int ni = 0; ni < 4; ni++)
                    mma8(acc[mi][ni], af[mi], bf[ni][0], bf[ni][1]);
        }
        __syncthreads();
        if (it + 2 < NIT) issue(cur, (it+2)*32);
    }

    // ---- epilogue ----
#pragma unroll
    for (int mi = 0; mi < MI; mi++) {
#pragma unroll
        for (int ni = 0; ni < 4; ni++) {
            int col = bn + wn + ni*8 + 2*lr;
            float bz0 = bias[col], bz1 = bias[col+1];
            int rA = bm + wm + mi*16 + lq;
            int rB = rA + 8;
            float a0 = acc[mi][ni][0] + bz0, a1 = acc[mi][ni][1] + bz1;
            float b0 = acc[mi][ni][2] + bz0, b1 = acc[mi][ni][3] + bz1;
            if (QKV) {
                int which = col >> 10, hh = (col >> 6) & 15, dd = col & 63;
                int bA = rA >> 11, nA = rA & 2047;
                int bB = rB >> 11, nB = rB & 2047;
                size_t baseA = ((size_t)(((which*2 + bA)*16 + hh))*2048 + nA)*64;
                size_t baseB = ((size_t)(((which*2 + bB)*16 + hh))*2048 + nB)*64;
                if (which < 2) {   // rotate q,k
                    int tiA = (nA << 6) + dd, tiB = (nB << 6) + dd;
                    float cA = g_cos[tiA], sA_ = g_sin[tiA], xA = g_xs[tiA];
                    float cB = g_cos[tiB], sB_ = g_sin[tiB], xB = g_xs[tiB];
                    float y0 = a0*cA - a1*sA_, y1 = a1*cA + a0*sA_;
                    float z0 = b0*cB - b1*sB_, z1 = b1*cB + b0*sB_;
                    if (which == 0) {   // q: *xs, pre-scale by 1/8 (exact on tf32)
                        a0 = y0*xA*0.125f; a1 = y1*xA*0.125f;
                        b0 = z0*xB*0.125f; b1 = z1*xB*0.125f;
                    } else {            // k: /xs
                        a0 = y0/xA; a1 = y1/xA; b0 = z0/xB; b1 = z1/xB;
                    }
                    // permuted scalar stores: logical (2lr,2lr+1) -> (p0, p0+2)
                    int p0 = (dd & ~7) + (((lr & 1) << 2) | (lr >> 1));
                    g_qkv[baseA + p0]     = f2tf(a0);
                    g_qkv[baseA + p0 + 2] = f2tf(a1);
                    g_qkv[baseB + p0]     = f2tf(b0);
                    g_qkv[baseB + p0 + 2] = f2tf(b1);
                } else {                // v: straight
                    uint2 uA; uA.x = f2tf(a0); uA.y = f2tf(a1);
                    uint2 uB; uB.x = f2tf(b0); uB.y = f2tf(b1);
                    *(uint2*)&g_qkv[baseA + dd] = uA;
                    *(uint2*)&g_qkv[baseB + dd] = uB;
                }
            } else {
                *(float2*)&out[(size_t)rA*NC + col] = make_float2(a0, a1);
                *(float2*)&out[(size_t)rB*NC + col] = make_float2(b0, b1);
            }
        }
    }
}

// ============================================================
// Kernel 3: flash attention, TF32 mma, cvt-free staging
//   Ks/Ps hold permuted tf32 (pairs adjacent -> uint2 frag loads)
//   Vs straight [token][d], scalar B-frag loads (conflict-free)
// ============================================================
#define FSTR 72
#define FLASH_SMEM (256*FSTR*4)

__global__ __launch_bounds__(256, 2) void flash_tf32_kernel() {
    extern __shared__ unsigned sm_u[];
    unsigned* Ks = sm_u;                 // [64][FSTR]
    unsigned* Vs = sm_u + 64*FSTR;       // [64][FSTR]
    unsigned* Ps = sm_u + 128*FSTR;      // [128][FSTR]

    int tid = threadIdx.x;
    int lane = tid & 31, warp = tid >> 5;
    int lq = lane >> 2, lr = lane & 3;
    int qt = blockIdx.x, bh = blockIdx.y;
    int b = bh >> 4, h = bh & 15;
    int r0 = warp * 16;

    const unsigned* Qg = g_qkv + ((size_t)((0*BATCH + b)*NHEADS + h))*NTOK*HDIM + (size_t)qt*128*HDIM;
    const unsigned* Kg = g_qkv + ((size_t)((1*BATCH + b)*NHEADS + h))*NTOK*HDIM;
    const unsigned* Vg = g_qkv + ((size_t)((2*BATCH + b)*NHEADS + h))*NTOK*HDIM;

    // stage Q (already tf32, scaled, permuted): straight copy
    {
        int r = tid >> 4, c4 = (tid & 15) << 2;
#pragma unroll
        for (int p = 0; p < 8; p++)
            *(uint4*)&Ps[(r + p*16)*FSTR + c4] = *(const uint4*)(Qg + (size_t)(r + p*16)*HDIM + c4);
    }
    __syncthreads();

    unsigned qf[8][4];
#pragma unroll
    for (int kk = 0; kk < 8; kk++) {
        uint2 u0 = *(const uint2*)&Ps[(r0 + lq)*FSTR + kk*8 + 2*lr];
        uint2 u1 = *(const uint2*)&Ps[(r0 + lq + 8)*FSTR + kk*8 + 2*lr];
        qf[kk][0] = u0.x; qf[kk][1] = u1.x; qf[kk][2] = u0.y; qf[kk][3] = u1.y;
    }

    float O[8][4];
    float mstate[2] = {-1e30f, -1e30f};
    float lstate[2] = {0.f, 0.f};
#pragma unroll
    for (int n = 0; n < 8; n++)
#pragma unroll
        for (int r = 0; r < 4; r++) O[n][r] = 0.f;

    int pp = ((lr & 1) << 2) | (lr >> 1);   // permuted position of logical 2lr

    for (int kt = 0; kt < NTOK/64; kt++) {
        __syncthreads();   // WAR on Ks/Vs/Ps
        {
            int r = tid >> 4, c4 = (tid & 15) << 2;
            const unsigned* kg = Kg + (size_t)kt*64*HDIM;
            const unsigned* vg = Vg + (size_t)kt*64*HDIM;
#pragma unroll
            for (int p = 0; p < 4; p++) {
                int t = r + p*16;
                *(uint4*)&Ks[t*FSTR + c4] = *(const uint4*)(kg + (size_t)t*HDIM + c4);
                *(uint4*)&Vs[t*FSTR + c4] = *(const uint4*)(vg + (size_t)t*HDIM + c4);
            }
        }
        __syncthreads();

        // ---- S = Q K^T ----
        float s[8][4];
#pragma unroll
        for (int n = 0; n < 8; n++) {
            s[n][0] = s[n][1] = s[n][2] = s[n][3] = 0.f;
            const unsigned* krow = &Ks[(n*8 + lq)*FSTR + 2*lr];
#pragma unroll
            for (int kk = 0; kk < 8; kk++) {
                uint2 kb = *(const uint2*)(krow + kk*8);
                mma8(s[n], qf[kk], kb.x, kb.y);
            }
        }

        // ---- online softmax ----
        float mA = -1e30f, mB = -1e30f;
#pragma unroll
        for (int n = 0; n < 8; n++) {
            mA = fmaxf(mA, fmaxf(s[n][0], s[n][1]));
            mB = fmaxf(mB, fmaxf(s[n][2], s[n][3]));
        }
        mA = fmaxf(mA, __shfl_xor_sync(0xffffffffu, mA, 1));
        mA = fmaxf(mA, __shfl_xor_sync(0xffffffffu, mA, 2));
        mB = fmaxf(mB, __shfl_xor_sync(0xffffffffu, mB, 1));
        mB = fmaxf(mB, __shfl_xor_sync(0xffffffffu, mB, 2));
        float mnA = fmaxf(mstate[0], mA), mnB = fmaxf(mstate[1], mB);
        float corrA = __expf(mstate[0] - mnA), corrB = __expf(mstate[1] - mnB);
        float sumA = 0.f, sumB = 0.f;
#pragma unroll
        for (int n = 0; n < 8; n++) {
            float p0 = __expf(s[n][0] - mnA), p1 = __expf(s[n][1] - mnA);
            float p2 = __expf(s[n][2] - mnB), p3 = __expf(s[n][3] - mnB);
            sumA += p0 + p1; sumB += p2 + p3;
            // permuted P store: logical (2lr, 2lr+1) -> (pp, pp+2)
            Ps[(r0 + lq)*FSTR + n*8 + pp]         = f2tf(p0);
            Ps[(r0 + lq)*FSTR + n*8 + pp + 2]     = f2tf(p1);
            Ps[(r0 + lq + 8)*FSTR + n*8 + pp]     = f2tf(p2);
            Ps[(r0 + lq + 8)*FSTR + n*8 + pp + 2] = f2tf(p3);
        }
        sumA += __shfl_xor_sync(0xffffffffu, sumA, 1);
        sumA += __shfl_xor_sync(0xffffffffu, sumA, 2);
        sumB += __shfl_xor_sync(0xffffffffu, sumB, 1);
        sumB += __shfl_xor_sync(0xffffffffu, sumB, 2);
        lstate[0] = lstate[0]*corrA + sumA; mstate[0] = mnA;
        lstate[1] = lstate[1]*corrB + sumB; mstate[1] = mnB;
#pragma unroll
        for (int n = 0; n < 8; n++) {
            O[n][0] *= corrA; O[n][1] *= corrA;
            O[n][2] *= corrB; O[n][3] *= corrB;
        }
        __syncwarp();

        // ---- O += P V ----
#pragma unroll
        for (int kk = 0; kk < 8; kk++) {
            unsigned pa[4];
            uint2 u0 = *(const uint2*)&Ps[(r0 + lq)*FSTR + kk*8 + 2*lr];
            uint2 u1 = *(const uint2*)&Ps[(r0 + lq + 8)*FSTR + kk*8 + 2*lr];
            pa[0] = u0.x; pa[1] = u1.x; pa[2] = u0.y; pa[3] = u1.y;
#pragma unroll
            for (int n = 0; n < 8; n++) {
                unsigned vb0 = Vs[(kk*8 + lr)*FSTR + n*8 + lq];
                unsigned vb1 = Vs[(kk*8 + lr + 4)*FSTR + n*8 + lq];
                mma8(O[n], pa, vb0, vb1);
            }
        }
    }

    // epilogue: normalize, tf32-round, permuted store into g_att
    float invA = 1.f / lstate[0], invB = 1.f / lstate[1];
    int rowA = qt*128 + r0 + lq;
    int rowB = rowA + 8;
#pragma unroll
    for (int n = 0; n < 8; n++) {
        int col = h*HDIM + n*8 + pp;
        size_t baseA = (size_t)(b*NTOK + rowA)*D_MODEL + col;
        size_t baseB = (size_t)(b*NTOK + rowB)*D_MODEL + col;
        g_att[baseA]     = f2tf(O[n][0]*invA);
        g_att[baseA + 2] = f2tf(O[n][1]*invA);
        g_att[baseB]     = f2tf(O[n][2]*invB);
        g_att[baseB + 2] = f2tf(O[n][3]*invB);
    }
}

// ============================================================
// launch
// ============================================================
extern "C" void kernel_launch(void* const* d_in, const int* in_sizes, int n_in,
                              void* d_out, int out_size) {
    const float* x      = (const float*)d_in[0];
    const float* w_qkv  = (const float*)d_in[1];
    const float* b_qkv  = (const float*)d_in[2];
    const float* w_proj = (const float*)d_in[3];
    const float* b_proj = (const float*)d_in[4];
    float* out = (float*)d_out;
    (void)in_sizes; (void)n_in; (void)out_size;

    rope_tables_kernel<<<(NTOK*HDIM)/256, 256>>>();

    const int NCONV = (MROWS*D_MODEL + D_MODEL*QKVCOLS + D_MODEL*D_MODEL)/4;
    preconvert_kernel<<<(NCONV + 255)/256, 256>>>(x, w_qkv, w_proj);

    cudaFuncSetAttribute(gemm_tf32_kernel<QKVCOLS, true, 128>,
                         cudaFuncAttributeMaxDynamicSharedMemorySize, GEMM_SMEM(128));
    gemm_tf32_kernel<QKVCOLS, true, 128>
        <<<dim3(QKVCOLS/128, MROWS/128), 256, GEMM_SMEM(128)>>>(b_qkv, nullptr);

    cudaFuncSetAttribute(flash_tf32_kernel,
                         cudaFuncAttributeMaxDynamicSharedMemorySize, FLASH_SMEM);
    flash_tf32_kernel<<<dim3(NTOK/128, BATCH*NHEADS), 256, FLASH_SMEM>>>();

    cudaFuncSetAttribute(gemm_tf32_kernel<D_MODEL, false, 64>,
                         cudaFuncAttributeMaxDynamicSharedMemorySize, GEMM_SMEM(64));
    gemm_tf32_kernel<D_MODEL, false, 64>
        <<<dim3(D_MODEL/128, MROWS/64), 256, GEMM_SMEM(64)>>>(b_proj, out);
}

// round 6
// speedup vs baseline: 1.3152x; 1.0595x over previous
#include <cuda_runtime.h>
#include <math.h>

// ---------------- problem constants ----------------
#define D_MODEL  1024
#define NHEADS   16
#define HDIM     64
#define NTOK     2048
#define BATCH    2
#define MROWS    (BATCH*NTOK)       // 4096
#define QKVCOLS  (3*D_MODEL)        // 3072

// ---------------- scratch (tf32 bit patterns) ----------------
__device__ unsigned g_qkv[3*BATCH*NHEADS*NTOK*HDIM]; // Q (rows natural, d-perm, prescaled), K (rows tau-perm, d-perm)
__device__ uint2    g_v2 [BATCH*NHEADS*1024*64];     // V pairs: [b,h][pr][d] = (V[n][d], V[n+8][d])
__device__ unsigned g_att[MROWS*D_MODEL];            // flash out, d-perm tf32
__device__ unsigned g_xt [MROWS*D_MODEL];            // X tf32, d-perm
__device__ unsigned g_wqi[(D_MODEL/8*4)*(QKVCOLS*2)]; // w_qkv tf32, k-pair interleaved
__device__ unsigned g_wpi[(D_MODEL/8*4)*(D_MODEL*2)]; // w_proj tf32, k-pair interleaved
__device__ float g_cos[NTOK*HDIM];
__device__ float g_sin[NTOK*HDIM];
__device__ float g_xs [NTOK*HDIM];

// ---------------- helpers ----------------
__device__ __forceinline__ unsigned f2tf(float f) {
    unsigned u;
    asm("cvt.rna.tf32.f32 %0, %1;" : "=r"(u) : "f"(f));
    return u;
}
__device__ __forceinline__ void mma8(float c[4], const unsigned a[4], unsigned b0, unsigned b1) {
    asm("mma.sync.aligned.m16n8k8.row.col.f32.tf32.tf32.f32 "
        "{%0,%1,%2,%3},{%4,%5,%6,%7},{%8,%9},{%0,%1,%2,%3};"
        : "+f"(c[0]), "+f"(c[1]), "+f"(c[2]), "+f"(c[3])
        : "r"(a[0]), "r"(a[1]), "r"(a[2]), "r"(a[3]), "r"(b0), "r"(b1));
}
__device__ __forceinline__ void cpa16(unsigned dst, const void* src) {
    asm volatile("cp.async.cg.shared.global [%0], [%1], 16;" :: "r"(dst), "l"(src));
}
__device__ __forceinline__ void cpa_commit() {
    asm volatile("cp.async.commit_group;");
}
template<int N>
__device__ __forceinline__ void cpa_wait() {
    asm volatile("cp.async.wait_group %0;" :: "n"(N));
}

// ============================================================
// Kernel 1: xpos/ND-RoPE tables (fp64, matches numpy ref)
// ============================================================
__global__ void rope_tables_kernel() {
    int idx = blockIdx.x * blockDim.x + threadIdx.x;
    if (idx >= NTOK*HDIM) return;
    int n = idx >> 6;
    int d = idx & 63;
    int axis = d >> 5;
    int jj   = d & 31;
    int p    = jj >> 1;
    double t, half;
    if (axis == 0) { t = (double)(n >> 6); half = 16.0; }
    else           { t = (double)(n & 63); half = 32.0; }
    double inv_freq = pow(10000.0, -((double)(2*p)) / 32.0);
    double f  = t * inv_freq;
    double sbase = ((double)(2*p) + 0.4*32.0) / (1.4*32.0);
    double power = (t - half) / 64.0;
    double sc = pow(sbase, power);
    g_cos[idx] = (float)cos(f);
    g_sin[idx] = (float)sin(f);
    g_xs [idx] = (float)sc;
}

// ============================================================
// Kernel 1b: preconvert
//   X -> g_xt (tf32, d-pair perm)
//   W -> g_w*i (tf32, rows (k,k+4) interleaved as uint2 pairs)
// ============================================================
__global__ void preconvert_kernel(const float* __restrict__ X,
                                  const float* __restrict__ Wq,
                                  const float* __restrict__ Wp) {
    const int NX  = MROWS*D_MODEL/4;            // 262144
    const int NQ  = (D_MODEL/8*4)*(QKVCOLS/4);  // 512*768
    const int NP  = (D_MODEL/8*4)*(D_MODEL/4);  // 512*256
    int i = blockIdx.x * blockDim.x + threadIdx.x;
    if (i < NX) {
        float4 v = ((const float4*)X)[i];
        int e = i << 2;
        int off = (e & ~7) + ((e & 4) >> 2);
        g_xt[off+0] = f2tf(v.x);
        g_xt[off+2] = f2tf(v.y);
        g_xt[off+4] = f2tf(v.z);
        g_xt[off+6] = f2tf(v.w);
    } else if (i < NX + NQ) {
        int j = i - NX;
        int prow = j / (QKVCOLS/4);
        int cg   = (j - prow*(QKVCOLS/4)) << 2;
        int k    = ((prow >> 2) << 3) + (prow & 3);
        float4 v0 = *(const float4*)(Wq + (size_t)k*QKVCOLS + cg);
        float4 v1 = *(const float4*)(Wq + (size_t)(k+4)*QKVCOLS + cg);
        unsigned* d = &g_wqi[(size_t)prow*(QKVCOLS*2) + cg*2];
        uint4 u0; u0.x=f2tf(v0.x); u0.y=f2tf(v1.x); u0.z=f2tf(v0.y); u0.w=f2tf(v1.y);
        uint4 u1; u1.x=f2tf(v0.z); u1.y=f2tf(v1.z); u1.z=f2tf(v0.w); u1.w=f2tf(v1.w);
        *(uint4*)(d)   = u0;
        *(uint4*)(d+4) = u1;
    } else {
        int j = i - NX - NQ;
        if (j < NP) {
            int prow = j / (D_MODEL/4);
            int cg   = (j - prow*(D_MODEL/4)) << 2;
            int k    = ((prow >> 2) << 3) + (prow & 3);
            float4 v0 = *(const float4*)(Wp + (size_t)k*D_MODEL + cg);
            float4 v1 = *(const float4*)(Wp + (size_t)(k+4)*D_MODEL + cg);
            unsigned* d = &g_wpi[(size_t)prow*(D_MODEL*2) + cg*2];
            uint4 u0; u0.x=f2tf(v0.x); u0.y=f2tf(v1.x); u0.z=f2tf(v0.y); u0.w=f2tf(v1.y);
            uint4 u1; u1.x=f2tf(v0.z); u1.y=f2tf(v1.z); u1.z=f2tf(v0.w); u1.w=f2tf(v1.w);
            *(uint4*)(d)   = u0;
            *(uint4*)(d+4) = u1;
        }
    }
}

// ============================================================
// Kernel 2: TF32 GEMM, TMx128 tile, 2-stage cp.async
//   A: pre-converted d-perm; B: k-pair interleaved (uint2 frags)
// ============================================================
#define AS_STR 40
#define BS_STR 264      // 16 rows of 256 data words + 8 pad
#define GEMM_SMEM(TM) ((2*(TM)*AS_STR + 2*16*BS_STR)*4)

template<int NC, bool QKV, int TM>
__global__ __launch_bounds__(256, 2) void gemm_tf32_kernel(
    const float* __restrict__ bias, float* __restrict__ out)
{
    constexpr int MI = TM/32;
    extern __shared__ unsigned gsm_u[];
    unsigned* As = gsm_u;                    // [2][TM][AS_STR]
    unsigned* Bs = gsm_u + 2*TM*AS_STR;      // [2][16][BS_STR]

    const unsigned* Ap = QKV ? g_xt : g_att;
    const unsigned* Bp = QKV ? g_wqi : g_wpi;

    int tid = threadIdx.x;
    int lane = tid & 31, warp = tid >> 5;
    int lq = lane >> 2, lr = lane & 3;
    int wm = (warp >> 2) * (TM/2);
    int wn = (warp & 3) * 32;
    int bm = blockIdx.y * TM, bn = blockIdx.x * 128;

    float acc[MI][4][4];
#pragma unroll
    for (int mi = 0; mi < MI; mi++)
#pragma unroll
        for (int ni = 0; ni < 4; ni++)
#pragma unroll
            for (int r = 0; r < 4; r++) acc[mi][ni][r] = 0.f;

    int ar = tid >> 3, ac = (tid & 7) << 2;

    unsigned sA = (unsigned)__cvta_generic_to_shared(As);
    unsigned sB = (unsigned)__cvta_generic_to_shared(Bs);

    auto issue = [&](int stage, int k0) {
        unsigned dA = sA + (unsigned)(stage*TM*AS_STR)*4;
        unsigned dB = sB + (unsigned)(stage*16*BS_STR)*4;
#pragma unroll
        for (int p = 0; p < MI; p++)
            cpa16(dA + (unsigned)((ar + p*32)*AS_STR + ac)*4,
                  Ap + (size_t)(bm + ar + p*32)*1024 + k0 + ac);
        // B: 16 interleaved rows x 256 words, rows (k0>>1)..+15, col off bn*2
#pragma unroll
        for (int p = 0; p < 4; p++) {
            int idx = p*256 + tid;
            int row = idx >> 6, c = (idx & 63) << 2;
            cpa16(dB + (unsigned)(row*BS_STR + c)*4,
                  Bp + (size_t)((k0>>1) + row)*(NC*2) + bn*2 + c);
        }
        cpa_commit();
    };

    issue(0, 0);
    issue(1, 32);

    const int NIT = 1024/32;
    for (int it = 0; it < NIT; it++) {
        int cur = it & 1;
        if (it + 2 < NIT) cpa_wait<1>(); else cpa_wait<0>();
        __syncthreads();

        const unsigned* Af = As + cur*TM*AS_STR;
        const unsigned* Bf = Bs + cur*16*BS_STR;
#pragma unroll
        for (int kk = 0; kk < 4; kk++) {
            unsigned af[MI][4];
            uint2 bf[4];
#pragma unroll
            for (int mi = 0; mi < MI; mi++) {
                int r = wm + mi*16 + lq;
                uint2 u0 = *(const uint2*)&Af[r*AS_STR + kk*8 + 2*lr];
                uint2 u1 = *(const uint2*)&Af[(r+8)*AS_STR + kk*8 + 2*lr];
                af[mi][0] = u0.x; af[mi][1] = u1.x;
                af[mi][2] = u0.y; af[mi][3] = u1.y;
            }
#pragma unroll
            for (int ni = 0; ni < 4; ni++)
                bf[ni] = *(const uint2*)&Bf[(kk*4 + lr)*BS_STR + (wn + ni*8 + lq)*2];
#pragma unroll
            for (int mi = 0; mi < MI; mi++)
#pragma unroll
                for (int ni = 0; ni < 4; ni++)
                    mma8(acc[mi][ni], af[mi], bf[ni].x, bf[ni].y);
        }
        __syncthreads();
        if (it + 2 < NIT) issue(cur, (it+2)*32);
    }

    // ---- epilogue ----
#pragma unroll
    for (int mi = 0; mi < MI; mi++) {
#pragma unroll
        for (int ni = 0; ni < 4; ni++) {
            int col = bn + wn + ni*8 + 2*lr;
            float bz0 = bias[col], bz1 = bias[col+1];
            int rA = bm + wm + mi*16 + lq;
            int rB = rA + 8;
            float a0 = acc[mi][ni][0] + bz0, a1 = acc[mi][ni][1] + bz1;
            float b0 = acc[mi][ni][2] + bz0, b1 = acc[mi][ni][3] + bz1;
            if (QKV) {
                int which = col >> 10, hh = (col >> 6) & 15, dd = col & 63;
                int bA = rA >> 11, nA = rA & 2047;
                int bB = rB >> 11, nB = rB & 2047;
                if (which < 2) {   // rotate q,k
                    int tiA = (nA << 6) + dd, tiB = (nB << 6) + dd;
                    float cA = g_cos[tiA], sA_ = g_sin[tiA], xA = g_xs[tiA];
                    float cB = g_cos[tiB], sB_ = g_sin[tiB], xB = g_xs[tiB];
                    float y0 = a0*cA - a1*sA_, y1 = a1*cA + a0*sA_;
                    float z0 = b0*cB - b1*sB_, z1 = b1*cB + b0*sB_;
                    int p0 = (dd & ~7) + (((lr & 1) << 2) | (lr >> 1));  // d-pair perm
                    if (which == 0) {   // Q: *xs, prescale 1/8, natural rows
                        a0 = y0*xA*0.125f; a1 = y1*xA*0.125f;
                        b0 = z0*xB*0.125f; b1 = z1*xB*0.125f;
                        size_t qA = ((size_t)((0 + bA)*16 + hh)*2048 + nA)*64;
                        size_t qB = ((size_t)((0 + bB)*16 + hh)*2048 + nB)*64;
                        g_qkv[qA + p0]     = f2tf(a0);
                        g_qkv[qA + p0 + 2] = f2tf(a1);
                        g_qkv[qB + p0]     = f2tf(b0);
                        g_qkv[qB + p0 + 2] = f2tf(b1);
                    } else {            // K: /xs, tau-permuted rows
                        a0 = y0/xA; a1 = y1/xA; b0 = z0/xB; b1 = z1/xB;
                        int lq3 = nA & 15;   // == lq, 0..7
                        int iA = (nA & ~63) + (((nA >> 4) & 3) << 4)
                               + ((lq3 >> 2) << 3) + (lq3 & 3);
                        int iB = iA + 4;     // token nB = nA+8
                        size_t kA = ((size_t)((2 + bA)*16 + hh)*2048 + iA)*64;
                        size_t kB = ((size_t)((2 + bB)*16 + hh)*2048 + iB)*64;
                        g_qkv[kA + p0]     = f2tf(a0);
                        g_qkv[kA + p0 + 2] = f2tf(a1);
                        g_qkv[kB + p0]     = f2tf(b0);
                        g_qkv[kB + p0 + 2] = f2tf(b1);
                    }
                } else {                // V: pair rows (nA, nA+8) interleaved
                    int pr = ((nA >> 4) << 3) + (nA & 7);
                    uint2* dst = &g_v2[((size_t)(bA*16 + hh)*1024 + pr)*64 + dd];
                    uint4 u; u.x = f2tf(a0); u.y = f2tf(b0);
                    u.z = f2tf(a1); u.w = f2tf(b1);
                    *(uint4*)dst = u;
                }
            } else {
                *(float2*)&out[(size_t)rA*NC + col] = make_float2(a0, a1);
                *(float2*)&out[(size_t)rB*NC + col] = make_float2(b0, b1);
            }
        }
    }
}

// ============================================================
// Kernel 3: flash attention, TF32 mma, cp.async double-buffered
//   Ks: [2][64][72]   K tile (internal token order, d-perm)
//   Vi: [2][32][136]  V pair rows (uint2 along token +8)
//   Ps: [128][72]     Q staging, then P
// ============================================================
#define KS_STR 72
#define VI_STR 136
#define FSTR   72
#define FLASH_SMEM ((2*64*KS_STR + 2*32*VI_STR + 128*FSTR)*4)   // 108544

__global__ __launch_bounds__(256, 2) void flash_tf32_kernel() {
    extern __shared__ unsigned sm_u[];
    unsigned* Ks = sm_u;                       // [2][64][KS_STR]
    unsigned* Vi = sm_u + 2*64*KS_STR;         // [2][32][VI_STR]
    unsigned* Ps = sm_u + 2*64*KS_STR + 2*32*VI_STR; // [128][FSTR]

    int tid = threadIdx.x;
    int lane = tid & 31, warp = tid >> 5;
    int lq = lane >> 2, lr = lane & 3;
    int qt = blockIdx.x, bh = blockIdx.y;
    int b = bh >> 4, h = bh & 15;
    int r0 = warp * 16;

    const unsigned* Qg = g_qkv + ((size_t)((0 + b)*16 + h))*NTOK*HDIM + (size_t)qt*128*HDIM;
    const unsigned* Kg = g_qkv + ((size_t)((2 + b)*16 + h))*NTOK*HDIM;
    const unsigned* Vg = (const unsigned*)(g_v2 + (size_t)(b*16 + h)*1024*64);

    unsigned sKs = (unsigned)__cvta_generic_to_shared(Ks);
    unsigned sVi = (unsigned)__cvta_generic_to_shared(Vi);

    auto issueKV = [&](int kt, int s) {
        const unsigned* kg = Kg + (size_t)kt*64*HDIM;       // 4096 words
        const unsigned* vg = Vg + (size_t)kt*32*128;        // 4096 words
#pragma unroll
        for (int p = 0; p < 4; p++) {
            int idx = p*256 + tid;
            int krow = idx >> 4, kc = (idx & 15) << 2;
            cpa16(sKs + (unsigned)((s*64 + krow)*KS_STR + kc)*4, kg + krow*64 + kc);
            int vrow = idx >> 5, vc = (idx & 31) << 2;
            cpa16(sVi + (unsigned)((s*32 + vrow)*VI_STR + vc)*4, vg + vrow*128 + vc);
        }
        cpa_commit();
    };

    issueKV(0, 0);
    issueKV(1, 1);

    // stage Q (tf32, scaled, d-perm): straight copy
    {
        int r = tid >> 4, c4 = (tid & 15) << 2;
#pragma unroll
        for (int p = 0; p < 8; p++)
            *(uint4*)&Ps[(r + p*16)*FSTR + c4] = *(const uint4*)(Qg + (size_t)(r + p*16)*HDIM + c4);
    }
    __syncthreads();

    unsigned qf[8][4];
#pragma unroll
    for (int kk = 0; kk < 8; kk++) {
        uint2 u0 = *(const uint2*)&Ps[(r0 + lq)*FSTR + kk*8 + 2*lr];
        uint2 u1 = *(const uint2*)&Ps[(r0 + lq + 8)*FSTR + kk*8 + 2*lr];
        qf[kk][0] = u0.x; qf[kk][1] = u1.x; qf[kk][2] = u0.y; qf[kk][3] = u1.y;
    }

    float O[8][4];
    float mstate[2] = {-1e30f, -1e30f};
    float lstate[2] = {0.f, 0.f};
#pragma unroll
    for (int n = 0; n < 8; n++)
#pragma unroll
        for (int r = 0; r < 4; r++) O[n][r] = 0.f;

    int pp = ((lr & 1) << 2) | (lr >> 1);   // permuted pos of logical 2lr

    const int NKT = NTOK/64;
    for (int kt = 0; kt < NKT; kt++) {
        int s = kt & 1;
        if (kt + 2 < NKT) cpa_wait<1>(); else cpa_wait<0>();
        __syncthreads();

        const unsigned* Kf = Ks + s*64*KS_STR;
        const unsigned* Vf = Vi + s*32*VI_STR;

        // ---- S = Q K^T ----
        float sc[8][4];
#pragma unroll
        for (int n = 0; n < 8; n++) {
            sc[n][0] = sc[n][1] = sc[n][2] = sc[n][3] = 0.f;
            const unsigned* krow = &Kf[(n*8 + lq)*KS_STR + 2*lr];
#pragma unroll
            for (int kk = 0; kk < 8; kk++) {
                uint2 kb = *(const uint2*)(krow + kk*8);
                mma8(sc[n], qf[kk], kb.x, kb.y);
            }
        }

        // ---- online softmax ----
        float mA = -1e30f, mB = -1e30f;
#pragma unroll
        for (int n = 0; n < 8; n++) {
            mA = fmaxf(mA, fmaxf(sc[n][0], sc[n][1]));
            mB = fmaxf(mB, fmaxf(sc[n][2], sc[n][3]));
        }
        mA = fmaxf(mA, __shfl_xor_sync(0xffffffffu, mA, 1));
        mA = fmaxf(mA, __shfl_xor_sync(0xffffffffu, mA, 2));
        mB = fmaxf(mB, __shfl_xor_sync(0xffffffffu, mB, 1));
        mB = fmaxf(mB, __shfl_xor_sync(0xffffffffu, mB, 2));
        float mnA = fmaxf(mstate[0], mA), mnB = fmaxf(mstate[1], mB);
        float corrA = __expf(mstate[0] - mnA), corrB = __expf(mstate[1] - mnB);
        float sumA = 0.f, sumB = 0.f;
#pragma unroll
        for (int n = 0; n < 8; n++) {
            float p0 = __expf(sc[n][0] - mnA), p1 = __expf(sc[n][1] - mnA);
            float p2 = __expf(sc[n][2] - mnB), p3 = __expf(sc[n][3] - mnB);
            sumA += p0 + p1; sumB += p2 + p3;
            Ps[(r0 + lq)*FSTR + n*8 + pp]         = f2tf(p0);
            Ps[(r0 + lq)*FSTR + n*8 + pp + 2]     = f2tf(p1);
            Ps[(r0 + lq + 8)*FSTR + n*8 + pp]     = f2tf(p2);
            Ps[(r0 + lq + 8)*FSTR + n*8 + pp + 2] = f2tf(p3);
        }
        sumA += __shfl_xor_sync(0xffffffffu, sumA, 1);
        sumA += __shfl_xor_sync(0xffffffffu, sumA, 2);
        sumB += __shfl_xor_sync(0xffffffffu, sumB, 1);
        sumB += __shfl_xor_sync(0xffffffffu, sumB, 2);
        lstate[0] = lstate[0]*corrA + sumA; mstate[0] = mnA;
        lstate[1] = lstate[1]*corrB + sumB; mstate[1] = mnB;
#pragma unroll
        for (int n = 0; n < 8; n++) {
            O[n][0] *= corrA; O[n][1] *= corrA;
            O[n][2] *= corrB; O[n][3] *= corrB;
        }
        __syncwarp();

        // ---- O += P V ----
#pragma unroll
        for (int kk = 0; kk < 8; kk++) {
            unsigned pa[4];
            uint2 u0 = *(const uint2*)&Ps[(r0 + lq)*FSTR + kk*8 + 2*lr];
            uint2 u1 = *(const uint2*)&Ps[(r0 + lq + 8)*FSTR + kk*8 + 2*lr];
            pa[0] = u0.x; pa[1] = u1.x; pa[2] = u0.y; pa[3] = u1.y;
            const unsigned* vrow = &Vf[(kk*4 + lr)*VI_STR];
#pragma unroll
            for (int n = 0; n < 8; n++) {
                uint2 vb = *(const uint2*)(vrow + (n*8 + lq)*2);
                mma8(O[n], pa, vb.x, vb.y);
            }
        }

        __syncthreads();
        if (kt + 2 < NKT) issueKV(kt + 2, s);
    }

    // epilogue: normalize, tf32-round, permuted store into g_att
    float invA = 1.f / lstate[0], invB = 1.f / lstate[1];
    int rowA = qt*128 + r0 + lq;
    int rowB = rowA + 8;
#pragma unroll
    for (int n = 0; n < 8; n++) {
        int col = h*HDIM + n*8 + pp;
        size_t baseA = (size_t)(b*NTOK + rowA)*D_MODEL + col;
        size_t baseB = (size_t)(b*NTOK + rowB)*D_MODEL + col;
        g_att[baseA]     = f2tf(O[n][0]*invA);
        g_att[baseA + 2] = f2tf(O[n][1]*invA);
        g_att[baseB]     = f2tf(O[n][2]*invB);
        g_att[baseB + 2] = f2tf(O[n][3]*invB);
    }
}

// ============================================================
// launch
// ============================================================
extern "C" void kernel_launch(void* const* d_in, const int* in_sizes, int n_in,
                              void* d_out, int out_size) {
    const float* x      = (const float*)d_in[0];
    const float* w_qkv  = (const float*)d_in[1];
    const float* b_qkv  = (const float*)d_in[2];
    const float* w_proj = (const float*)d_in[3];
    const float* b_proj = (const float*)d_in[4];
    float* out = (float*)d_out;
    (void)in_sizes; (void)n_in; (void)out_size;

    rope_tables_kernel<<<(NTOK*HDIM)/256, 256>>>();

    const int NCONV = MROWS*D_MODEL/4 + (D_MODEL/8*4)*(QKVCOLS/4) + (D_MODEL/8*4)*(D_MODEL/4);
    preconvert_kernel<<<(NCONV + 255)/256, 256>>>(x, w_qkv, w_proj);

    cudaFuncSetAttribute(gemm_tf32_kernel<QKVCOLS, true, 128>,
                         cudaFuncAttributeMaxDynamicSharedMemorySize, GEMM_SMEM(128));
    gemm_tf32_kernel<QKVCOLS, true, 128>
        <<<dim3(QKVCOLS/128, MROWS/128), 256, GEMM_SMEM(128)>>>(b_qkv, nullptr);

    cudaFuncSetAttribute(flash_tf32_kernel,
                         cudaFuncAttributeMaxDynamicSharedMemorySize, FLASH_SMEM);
    flash_tf32_kernel<<<dim3(NTOK/128, BATCH*NHEADS), 256, FLASH_SMEM>>>();

    cudaFuncSetAttribute(gemm_tf32_kernel<D_MODEL, false, 64>,
                         cudaFuncAttributeMaxDynamicSharedMemorySize, GEMM_SMEM(64));
    gemm_tf32_kernel<D_MODEL, false, 64>
        <<<dim3(D_MODEL/128, MROWS/64), 256, GEMM_SMEM(64)>>>(b_proj, out);
}

// round 8
// speedup vs baseline: 1.3228x; 1.0058x over previous
#include <cuda_runtime.h>
#include <math.h>

// ---------------- problem constants ----------------
#define D_MODEL  1024
#define NHEADS   16
#define HDIM     64
#define NTOK     2048
#define BATCH    2
#define MROWS    (BATCH*NTOK)       // 4096
#define QKVCOLS  (3*D_MODEL)        // 3072

// ---------------- scratch (tf32 bit patterns) ----------------
__device__ unsigned g_qkv[3*BATCH*NHEADS*NTOK*HDIM]; // Q (old d-perm, prescaled), K (tau rows, kk-interleaved d)
__device__ uint2    g_v2 [BATCH*NHEADS*1024*64];     // V pairs: [b,h][pr][d] = (V[n][d], V[n+8][d])
__device__ unsigned g_att[MROWS*D_MODEL];            // flash out, old d-perm tf32
__device__ unsigned g_xt [MROWS*D_MODEL];            // X tf32, old d-perm
__device__ unsigned g_wqi[(D_MODEL/8*4)*(QKVCOLS*2)]; // w_qkv tf32, k-pair interleaved
__device__ unsigned g_wpi[(D_MODEL/8*4)*(D_MODEL*2)]; // w_proj tf32, k-pair interleaved
__device__ float g_cos[NTOK*HDIM];
__device__ float g_sin[NTOK*HDIM];
__device__ float g_xs [NTOK*HDIM];

// ---------------- helpers ----------------
__device__ __forceinline__ unsigned f2tf(float f) {
    unsigned u;
    asm("cvt.rna.tf32.f32 %0, %1;" : "=r"(u) : "f"(f));
    return u;
}
__device__ __forceinline__ void mma8(float c[4], const unsigned a[4], unsigned b0, unsigned b1) {
    asm("mma.sync.aligned.m16n8k8.row.col.f32.tf32.tf32.f32 "
        "{%0,%1,%2,%3},{%4,%5,%6,%7},{%8,%9},{%0,%1,%2,%3};"
        : "+f"(c[0]), "+f"(c[1]), "+f"(c[2]), "+f"(c[3])
        : "r"(a[0]), "r"(a[1]), "r"(a[2]), "r"(a[3]), "r"(b0), "r"(b1));
}
__device__ __forceinline__ void cpa16(unsigned dst, const void* src) {
    asm volatile("cp.async.cg.shared.global [%0], [%1], 16;" :: "r"(dst), "l"(src));
}
__device__ __forceinline__ void cpa_commit() {
    asm volatile("cp.async.commit_group;");
}
template<int N>
__device__ __forceinline__ void cpa_wait() {
    asm volatile("cp.async.wait_group %0;" :: "n"(N));
}

// ============================================================
// Kernel 1: xpos/ND-RoPE tables (fp64, matches numpy ref)
// ============================================================
__global__ void rope_tables_kernel() {
    int idx = blockIdx.x * blockDim.x + threadIdx.x;
    if (idx >= NTOK*HDIM) return;
    int n = idx >> 6;
    int d = idx & 63;
    int axis = d >> 5;
    int jj   = d & 31;
    int p    = jj >> 1;
    double t, half;
    if (axis == 0) { t = (double)(n >> 6); half = 16.0; }
    else           { t = (double)(n & 63); half = 32.0; }
    double inv_freq = pow(10000.0, -((double)(2*p)) / 32.0);
    double f  = t * inv_freq;
    double sbase = ((double)(2*p) + 0.4*32.0) / (1.4*32.0);
    double power = (t - half) / 64.0;
    double sc = pow(sbase, power);
    g_cos[idx] = (float)cos(f);
    g_sin[idx] = (float)sin(f);
    g_xs [idx] = (float)sc;
}

// ============================================================
// Kernel 1b: preconvert X (old d-perm) and weights (k-pair interleaved)
// ============================================================
__global__ void preconvert_kernel(const float* __restrict__ X,
                                  const float* __restrict__ Wq,
                                  const float* __restrict__ Wp) {
    const int NX  = MROWS*D_MODEL/4;
    const int NQ  = (D_MODEL/8*4)*(QKVCOLS/4);
    const int NP  = (D_MODEL/8*4)*(D_MODEL/4);
    int i = blockIdx.x * blockDim.x + threadIdx.x;
    if (i < NX) {
        float4 v = ((const float4*)X)[i];
        int e = i << 2;
        int off = (e & ~7) + ((e & 4) >> 2);
        g_xt[off+0] = f2tf(v.x);
        g_xt[off+2] = f2tf(v.y);
        g_xt[off+4] = f2tf(v.z);
        g_xt[off+6] = f2tf(v.w);
    } else if (i < NX + NQ) {
        int j = i - NX;
        int prow = j / (QKVCOLS/4);
        int cg   = (j - prow*(QKVCOLS/4)) << 2;
        int k    = ((prow >> 2) << 3) + (prow & 3);
        float4 v0 = *(const float4*)(Wq + (size_t)k*QKVCOLS + cg);
        float4 v1 = *(const float4*)(Wq + (size_t)(k+4)*QKVCOLS + cg);
        unsigned* d = &g_wqi[(size_t)prow*(QKVCOLS*2) + cg*2];
        uint4 u0; u0.x=f2tf(v0.x); u0.y=f2tf(v1.x); u0.z=f2tf(v0.y); u0.w=f2tf(v1.y);
        uint4 u1; u1.x=f2tf(v0.z); u1.y=f2tf(v1.z); u1.z=f2tf(v0.w); u1.w=f2tf(v1.w);
        *(uint4*)(d)   = u0;
        *(uint4*)(d+4) = u1;
    } else {
        int j = i - NX - NQ;
        if (j < NP) {
            int prow = j / (D_MODEL/4);
            int cg   = (j - prow*(D_MODEL/4)) << 2;
            int k    = ((prow >> 2) << 3) + (prow & 3);
            float4 v0 = *(const float4*)(Wp + (size_t)k*D_MODEL + cg);
            float4 v1 = *(const float4*)(Wp + (size_t)(k+4)*D_MODEL + cg);
            unsigned* d = &g_wpi[(size_t)prow*(D_MODEL*2) + cg*2];
            uint4 u0; u0.x=f2tf(v0.x); u0.y=f2tf(v1.x); u0.z=f2tf(v0.y); u0.w=f2tf(v1.y);
            uint4 u1; u1.x=f2tf(v0.z); u1.y=f2tf(v1.z); u1.z=f2tf(v0.w); u1.w=f2tf(v1.w);
            *(uint4*)(d)   = u0;
            *(uint4*)(d+4) = u1;
        }
    }
}

// ============================================================
// Kernel 2: TF32 GEMM (as R6), K epilogue uses kk-interleaved d-layout
// ============================================================
#define AS_STR 40
#define BS_STR 264
#define GEMM_SMEM(TM) ((2*(TM)*AS_STR + 2*16*BS_STR)*4)

template<int NC, bool QKV, int TM>
__global__ __launch_bounds__(256, 2) void gemm_tf32_kernel(
    const float* __restrict__ bias, float* __restrict__ out)
{
    constexpr int MI = TM/32;
    extern __shared__ unsigned gsm_u[];
    unsigned* As = gsm_u;                    // [2][TM][AS_STR]
    unsigned* Bs = gsm_u + 2*TM*AS_STR;      // [2][16][BS_STR]

    const unsigned* Ap = QKV ? g_xt : g_att;
    const unsigned* Bp = QKV ? g_wqi : g_wpi;

    int tid = threadIdx.x;
    int lane = tid & 31, warp = tid >> 5;
    int lq = lane >> 2, lr = lane & 3;
    int wm = (warp >> 2) * (TM/2);
    int wn = (warp & 3) * 32;
    int bm = blockIdx.y * TM, bn = blockIdx.x * 128;

    float acc[MI][4][4];
#pragma unroll
    for (int mi = 0; mi < MI; mi++)
#pragma unroll
        for (int ni = 0; ni < 4; ni++)
#pragma unroll
            for (int r = 0; r < 4; r++) acc[mi][ni][r] = 0.f;

    int ar = tid >> 3, ac = (tid & 7) << 2;

    unsigned sA = (unsigned)__cvta_generic_to_shared(As);
    unsigned sB = (unsigned)__cvta_generic_to_shared(Bs);

    auto issue = [&](int stage, int k0) {
        unsigned dA = sA + (unsigned)(stage*TM*AS_STR)*4;
        unsigned dB = sB + (unsigned)(stage*16*BS_STR)*4;
#pragma unroll
        for (int p = 0; p < MI; p++)
            cpa16(dA + (unsigned)((ar + p*32)*AS_STR + ac)*4,
                  Ap + (size_t)(bm + ar + p*32)*1024 + k0 + ac);
#pragma unroll
        for (int p = 0; p < 4; p++) {
            int idx = p*256 + tid;
            int row = idx >> 6, c = (idx & 63) << 2;
            cpa16(dB + (unsigned)(row*BS_STR + c)*4,
                  Bp + (size_t)((k0>>1) + row)*(NC*2) + bn*2 + c);
        }
        cpa_commit();
    };

    issue(0, 0);
    issue(1, 32);

    const int NIT = 1024/32;
    for (int it = 0; it < NIT; it++) {
        int cur = it & 1;
        if (it + 2 < NIT) cpa_wait<1>(); else cpa_wait<0>();
        __syncthreads();

        const unsigned* Af = As + cur*TM*AS_STR;
        const unsigned* Bf = Bs + cur*16*BS_STR;
#pragma unroll
        for (int kk = 0; kk < 4; kk++) {
            unsigned af[MI][4];
            uint2 bf[4];
#pragma unroll
            for (int mi = 0; mi < MI; mi++) {
                int r = wm + mi*16 + lq;
                uint2 u0 = *(const uint2*)&Af[r*AS_STR + kk*8 + 2*lr];
                uint2 u1 = *(const uint2*)&Af[(r+8)*AS_STR + kk*8 + 2*lr];
                af[mi][0] = u0.x; af[mi][1] = u1.x;
                af[mi][2] = u0.y; af[mi][3] = u1.y;
            }
#pragma unroll
            for (int ni = 0; ni < 4; ni++)
                bf[ni] = *(const uint2*)&Bf[(kk*4 + lr)*BS_STR + (wn + ni*8 + lq)*2];
#pragma unroll
            for (int mi = 0; mi < MI; mi++)
#pragma unroll
                for (int ni = 0; ni < 4; ni++)
                    mma8(acc[mi][ni], af[mi], bf[ni].x, bf[ni].y);
        }
        __syncthreads();
        if (it + 2 < NIT) issue(cur, (it+2)*32);
    }

    // ---- epilogue ----
#pragma unroll
    for (int mi = 0; mi < MI; mi++) {
#pragma unroll
        for (int ni = 0; ni < 4; ni++) {
            int col = bn + wn + ni*8 + 2*lr;
            float bz0 = bias[col], bz1 = bias[col+1];
            int rA = bm + wm + mi*16 + lq;
            int rB = rA + 8;
            float a0 = acc[mi][ni][0] + bz0, a1 = acc[mi][ni][1] + bz1;
            float b0 = acc[mi][ni][2] + bz0, b1 = acc[mi][ni][3] + bz1;
            if (QKV) {
                int which = col >> 10, hh = (col >> 6) & 15, dd = col & 63;
                int bA = rA >> 11, nA = rA & 2047;
                int bB = rB >> 11, nB = rB & 2047;
                if (which < 2) {   // rotate q,k
                    int tiA = (nA << 6) + dd, tiB = (nB << 6) + dd;
                    float cA = g_cos[tiA], sA_ = g_sin[tiA], xA = g_xs[tiA];
                    float cB = g_cos[tiB], sB_ = g_sin[tiB], xB = g_xs[tiB];
                    float y0 = a0*cA - a1*sA_, y1 = a1*cA + a0*sA_;
                    float z0 = b0*cB - b1*sB_, z1 = b1*cB + b0*sB_;
                    if (which == 0) {   // Q: *xs, prescale 1/8, natural rows, OLD d-perm
                        a0 = y0*xA*0.125f; a1 = y1*xA*0.125f;
                        b0 = z0*xB*0.125f; b1 = z1*xB*0.125f;
                        int p0 = (dd & ~7) + (((lr & 1) << 2) | (lr >> 1));
                        size_t qA = ((size_t)((0 + bA)*16 + hh)*2048 + nA)*64;
                        size_t qB = ((size_t)((0 + bB)*16 + hh)*2048 + nB)*64;
                        g_qkv[qA + p0]     = f2tf(a0);
                        g_qkv[qA + p0 + 2] = f2tf(a1);
                        g_qkv[qB + p0]     = f2tf(b0);
                        g_qkv[qB + p0 + 2] = f2tf(b1);
                    } else {            // K: /xs, tau rows, kk-interleaved d-layout
                        a0 = y0/xA; a1 = y1/xA; b0 = z0/xB; b1 = z1/xB;
                        int lq3 = nA & 15;
                        int iA = (nA & ~63) + (((nA >> 4) & 3) << 4)
                               + ((lq3 >> 2) << 3) + (lq3 & 3);
                        int iB = iA + 4;
                        int bb   = 16*(dd >> 4) + 2*((dd >> 3) & 1);
                        int off0 = bb + 8*(lr & 1) + (lr >> 1);
                        size_t kA = ((size_t)((2 + bA)*16 + hh)*2048 + iA)*64;
                        size_t kB = ((size_t)((2 + bB)*16 + hh)*2048 + iB)*64;
                        g_qkv[kA + off0]     = f2tf(a0);
                        g_qkv[kA + off0 + 4] = f2tf(a1);
                        g_qkv[kB + off0]     = f2tf(b0);
                        g_qkv[kB + off0 + 4] = f2tf(b1);
                    }
                } else {                // V: pair rows (nA, nA+8) interleaved
                    int pr = ((nA >> 4) << 3) + (nA & 7);
                    uint2* dst = &g_v2[((size_t)(bA*16 + hh)*1024 + pr)*64 + dd];
                    uint4 u; u.x = f2tf(a0); u.y = f2tf(b0);
                    u.z = f2tf(a1); u.w = f2tf(b1);
                    *(uint4*)dst = u;
                }
            } else {
                *(float2*)&out[(size_t)rA*NC + col] = make_float2(a0, a1);
                *(float2*)&out[(size_t)rB*NC + col] = make_float2(b0, b1);
            }
        }
    }
}

// ============================================================
// Kernel 3: flash attention — 4 warps x 32 q-rows, dual m-tile,
//   LDS.128 K frags, cp.async double-buffered K/V.
//   FIXED staging: 8 passes x 128 threads = full 16KB per tile.
// ============================================================
#define KS_STR 80
#define VI_STR 136
#define FSTR   72
#define FLASH_SMEM ((2*64*KS_STR + 2*32*VI_STR + 128*FSTR)*4)   // 112640

__global__ __launch_bounds__(128, 2) void flash_tf32_kernel() {
    extern __shared__ unsigned sm_u[];
    unsigned* Ks = sm_u;                             // [2][64][80]
    unsigned* Vi = sm_u + 2*64*KS_STR;               // [2][32][136]
    unsigned* Ps = sm_u + 2*64*KS_STR + 2*32*VI_STR; // [128][72]

    int tid = threadIdx.x;
    int lane = tid & 31, warp = tid >> 5;   // 4 warps
    int lq = lane >> 2, lr = lane & 3;
    int qt = blockIdx.x, bh = blockIdx.y;
    int b = bh >> 4, h = bh & 15;
    int r0 = warp * 32;

    const unsigned* Qg = g_qkv + ((size_t)((0 + b)*16 + h))*NTOK*HDIM + (size_t)qt*128*HDIM;
    const unsigned* Kg = g_qkv + ((size_t)((2 + b)*16 + h))*NTOK*HDIM;
    const unsigned* Vg = (const unsigned*)(g_v2 + (size_t)(b*16 + h)*1024*64);

    unsigned sKs = (unsigned)__cvta_generic_to_shared(Ks);
    unsigned sVi = (unsigned)__cvta_generic_to_shared(Vi);

    auto issueKV = [&](int kt, int s) {
        const unsigned* kg = Kg + (size_t)kt*64*HDIM;
        const unsigned* vg = Vg + (size_t)kt*32*128;
#pragma unroll
        for (int p = 0; p < 8; p++) {
            int idx = p*128 + tid;                    // 0..1023
            int krow = idx >> 4, kc = (idx & 15) << 2; // 64 rows x 16 chunks
            cpa16(sKs + (unsigned)((s*64 + krow)*KS_STR + kc)*4, kg + krow*64 + kc);
            int vrow = idx >> 5, vc = (idx & 31) << 2; // 32 rows x 32 chunks
            cpa16(sVi + (unsigned)((s*32 + vrow)*VI_STR + vc)*4, vg + vrow*128 + vc);
        }
        cpa_commit();
    };

    issueKV(0, 0);
    issueKV(1, 1);

    // Q fragments straight from gmem (old d-perm: pairs adjacent at 2lr)
    unsigned qf[2][8][4];
#pragma unroll
    for (int mt = 0; mt < 2; mt++)
#pragma unroll
        for (int kk = 0; kk < 8; kk++) {
            uint2 u0 = *(const uint2*)(Qg + (size_t)(r0 + mt*16 + lq)*HDIM + kk*8 + 2*lr);
            uint2 u1 = *(const uint2*)(Qg + (size_t)(r0 + mt*16 + lq + 8)*HDIM + kk*8 + 2*lr);
            qf[mt][kk][0] = u0.x; qf[mt][kk][1] = u1.x;
            qf[mt][kk][2] = u0.y; qf[mt][kk][3] = u1.y;
        }

    float O[2][8][4];
    float mst[4] = {-1e30f, -1e30f, -1e30f, -1e30f};
    float lst[4] = {0.f, 0.f, 0.f, 0.f};
#pragma unroll
    for (int mt = 0; mt < 2; mt++)
#pragma unroll
        for (int n = 0; n < 8; n++)
#pragma unroll
            for (int r = 0; r < 4; r++) O[mt][n][r] = 0.f;

    int pp = ((lr & 1) << 2) | (lr >> 1);

    const int NKT = NTOK/64;
    for (int kt = 0; kt < NKT; kt++) {
        int s = kt & 1;
        if (kt + 2 < NKT) cpa_wait<1>(); else cpa_wait<0>();
        __syncthreads();

        const unsigned* Kf = Ks + s*64*KS_STR;
        const unsigned* Vf = Vi + s*32*VI_STR;

        // ---- S = Q K^T, both m-tiles per K fragment ----
        float s0[8][4], s1[8][4];
#pragma unroll
        for (int n = 0; n < 8; n++) {
            s0[n][0]=s0[n][1]=s0[n][2]=s0[n][3]=0.f;
            s1[n][0]=s1[n][1]=s1[n][2]=s1[n][3]=0.f;
            const unsigned* krow = &Kf[(n*8 + lq)*KS_STR + 4*lr];
#pragma unroll
            for (int kkp = 0; kkp < 4; kkp++) {
                uint4 kb = *(const uint4*)(krow + kkp*16);
                mma8(s0[n], qf[0][2*kkp],   kb.x, kb.y);
                mma8(s0[n], qf[0][2*kkp+1], kb.z, kb.w);
                mma8(s1[n], qf[1][2*kkp],   kb.x, kb.y);
                mma8(s1[n], qf[1][2*kkp+1], kb.z, kb.w);
            }
        }

        // ---- online softmax: 4 row-groups (mt0:A,B  mt1:C,D) ----
        float mA=-1e30f, mB=-1e30f, mC=-1e30f, mD=-1e30f;
#pragma unroll
        for (int n = 0; n < 8; n++) {
            mA = fmaxf(mA, fmaxf(s0[n][0], s0[n][1]));
            mB = fmaxf(mB, fmaxf(s0[n][2], s0[n][3]));
            mC = fmaxf(mC, fmaxf(s1[n][0], s1[n][1]));
            mD = fmaxf(mD, fmaxf(s1[n][2], s1[n][3]));
        }
        mA = fmaxf(mA, __shfl_xor_sync(0xffffffffu, mA, 1));
        mA = fmaxf(mA, __shfl_xor_sync(0xffffffffu, mA, 2));
        mB = fmaxf(mB, __shfl_xor_sync(0xffffffffu, mB, 1));
        mB = fmaxf(mB, __shfl_xor_sync(0xffffffffu, mB, 2));
        mC = fmaxf(mC, __shfl_xor_sync(0xffffffffu, mC, 1));
        mC = fmaxf(mC, __shfl_xor_sync(0xffffffffu, mC, 2));
        mD = fmaxf(mD, __shfl_xor_sync(0xffffffffu, mD, 1));
        mD = fmaxf(mD, __shfl_xor_sync(0xffffffffu, mD, 2));
        float mnA = fmaxf(mst[0], mA), mnB = fmaxf(mst[1], mB);
        float mnC = fmaxf(mst[2], mC), mnD = fmaxf(mst[3], mD);
        float cA = __expf(mst[0]-mnA), cB = __expf(mst[1]-mnB);
        float cC = __expf(mst[2]-mnC), cD = __expf(mst[3]-mnD);
        float sA=0.f, sB=0.f, sC=0.f, sD=0.f;
#pragma unroll
        for (int n = 0; n < 8; n++) {
            float p0 = __expf(s0[n][0]-mnA), p1 = __expf(s0[n][1]-mnA);
            float p2 = __expf(s0[n][2]-mnB), p3 = __expf(s0[n][3]-mnB);
            float p4 = __expf(s1[n][0]-mnC), p5 = __expf(s1[n][1]-mnC);
            float p6 = __expf(s1[n][2]-mnD), p7 = __expf(s1[n][3]-mnD);
            sA += p0+p1; sB += p2+p3; sC += p4+p5; sD += p6+p7;
            Ps[(r0 + lq)*FSTR      + n*8 + pp]     = f2tf(p0);
            Ps[(r0 + lq)*FSTR      + n*8 + pp + 2] = f2tf(p1);
            Ps[(r0 + lq + 8)*FSTR  + n*8 + pp]     = f2tf(p2);
            Ps[(r0 + lq + 8)*FSTR  + n*8 + pp + 2] = f2tf(p3);
            Ps[(r0 + lq + 16)*FSTR + n*8 + pp]     = f2tf(p4);
            Ps[(r0 + lq + 16)*FSTR + n*8 + pp + 2] = f2tf(p5);
            Ps[(r0 + lq + 24)*FSTR + n*8 + pp]     = f2tf(p6);
            Ps[(r0 + lq + 24)*FSTR + n*8 + pp + 2] = f2tf(p7);
        }
        sA += __shfl_xor_sync(0xffffffffu, sA, 1);
        sA += __shfl_xor_sync(0xffffffffu, sA, 2);
        sB += __shfl_xor_sync(0xffffffffu, sB, 1);
        sB += __shfl_xor_sync(0xffffffffu, sB, 2);
        sC += __shfl_xor_sync(0xffffffffu, sC, 1);
        sC += __shfl_xor_sync(0xffffffffu, sC, 2);
        sD += __shfl_xor_sync(0xffffffffu, sD, 1);
        sD += __shfl_xor_sync(0xffffffffu, sD, 2);
        lst[0] = lst[0]*cA + sA; mst[0] = mnA;
        lst[1] = lst[1]*cB + sB; mst[1] = mnB;
        lst[2] = lst[2]*cC + sC; mst[2] = mnC;
        lst[3] = lst[3]*cD + sD; mst[3] = mnD;
#pragma unroll
        for (int n = 0; n < 8; n++) {
            O[0][n][0] *= cA; O[0][n][1] *= cA;
            O[0][n][2] *= cB; O[0][n][3] *= cB;
            O[1][n][0] *= cC; O[1][n][1] *= cC;
            O[1][n][2] *= cD; O[1][n][3] *= cD;
        }
        __syncwarp();

        // ---- O += P V : V fragment read once, used for both m-tiles ----
#pragma unroll
        for (int kk = 0; kk < 8; kk++) {
            unsigned pa0[4], pa1[4];
            uint2 u0 = *(const uint2*)&Ps[(r0 + lq)*FSTR      + kk*8 + 2*lr];
            uint2 u1 = *(const uint2*)&Ps[(r0 + lq + 8)*FSTR  + kk*8 + 2*lr];
            uint2 u2 = *(const uint2*)&Ps[(r0 + lq + 16)*FSTR + kk*8 + 2*lr];
            uint2 u3 = *(const uint2*)&Ps[(r0 + lq + 24)*FSTR + kk*8 + 2*lr];
            pa0[0] = u0.x; pa0[1] = u1.x; pa0[2] = u0.y; pa0[3] = u1.y;
            pa1[0] = u2.x; pa1[1] = u3.x; pa1[2] = u2.y; pa1[3] = u3.y;
            const unsigned* vrow = &Vf[(kk*4 + lr)*VI_STR];
#pragma unroll
            for (int n = 0; n < 8; n++) {
                uint2 vb = *(const uint2*)(vrow + (n*8 + lq)*2);
                mma8(O[0][n], pa0, vb.x, vb.y);
                mma8(O[1][n], pa1, vb.x, vb.y);
            }
        }

        __syncthreads();
        if (kt + 2 < NKT) issueKV(kt + 2, s);
    }

    // epilogue: normalize, tf32-round, old-perm store into g_att
    float iA = 1.f/lst[0], iB = 1.f/lst[1], iC = 1.f/lst[2], iD = 1.f/lst[3];
    int rowA = qt*128 + r0 + lq;
#pragma unroll
    for (int n = 0; n < 8; n++) {
        int col = h*HDIM + n*8 + pp;
        size_t b0 = (size_t)(b*NTOK + rowA)*D_MODEL + col;
        size_t b1 = (size_t)(b*NTOK + rowA + 8)*D_MODEL + col;
        size_t b2 = (size_t)(b*NTOK + rowA + 16)*D_MODEL + col;
        size_t b3 = (size_t)(b*NTOK + rowA + 24)*D_MODEL + col;
        g_att[b0]     = f2tf(O[0][n][0]*iA);
        g_att[b0 + 2] = f2tf(O[0][n][1]*iA);
        g_att[b1]     = f2tf(O[0][n][2]*iB);
        g_att[b1 + 2] = f2tf(O[0][n][3]*iB);
        g_att[b2]     = f2tf(O[1][n][0]*iC);
        g_att[b2 + 2] = f2tf(O[1][n][1]*iC);
        g_att[b3]     = f2tf(O[1][n][2]*iD);
        g_att[b3 + 2] = f2tf(O[1][n][3]*iD);
    }
}

// ============================================================
// launch
// ============================================================
extern "C" void kernel_launch(void* const* d_in, const int* in_sizes, int n_in,
                              void* d_out, int out_size) {
    const float* x      = (const float*)d_in[0];
    const float* w_qkv  = (const float*)d_in[1];
    const float* b_qkv  = (const float*)d_in[2];
    const float* w_proj = (const float*)d_in[3];
    const float* b_proj = (const float*)d_in[4];
    float* out = (float*)d_out;
    (void)in_sizes; (void)n_in; (void)out_size;

    rope_tables_kernel<<<(NTOK*HDIM)/256, 256>>>();

    const int NCONV = MROWS*D_MODEL/4 + (D_MODEL/8*4)*(QKVCOLS/4) + (D_MODEL/8*4)*(D_MODEL/4);
    preconvert_kernel<<<(NCONV + 255)/256, 256>>>(x, w_qkv, w_proj);

    cudaFuncSetAttribute(gemm_tf32_kernel<QKVCOLS, true, 128>,
                         cudaFuncAttributeMaxDynamicSharedMemorySize, GEMM_SMEM(128));
    gemm_tf32_kernel<QKVCOLS, true, 128>
        <<<dim3(QKVCOLS/128, MROWS/128), 256, GEMM_SMEM(128)>>>(b_qkv, nullptr);

    cudaFuncSetAttribute(flash_tf32_kernel,
                         cudaFuncAttributeMaxDynamicSharedMemorySize, FLASH_SMEM);
    flash_tf32_kernel<<<dim3(NTOK/128, BATCH*NHEADS), 128, FLASH_SMEM>>>();

    cudaFuncSetAttribute(gemm_tf32_kernel<D_MODEL, false, 64>,
                         cudaFuncAttributeMaxDynamicSharedMemorySize, GEMM_SMEM(64));
    gemm_tf32_kernel<D_MODEL, false, 64>
        <<<dim3(D_MODEL/128, MROWS/64), 256, GEMM_SMEM(64)>>>(b_proj, out);
}

// round 9
// speedup vs baseline: 1.4089x; 1.0651x over previous
#include <cuda_runtime.h>
#include <math.h>

// ---------------- problem constants ----------------
#define D_MODEL  1024
#define NHEADS   16
#define HDIM     64
#define NTOK     2048
#define BATCH    2
#define MROWS    (BATCH*NTOK)       // 4096
#define QKVCOLS  (3*D_MODEL)        // 3072

// ---------------- scratch (tf32 bit patterns) ----------------
__device__ unsigned g_qkv[3*BATCH*NHEADS*NTOK*HDIM]; // Q (natural rows, old d-perm, prescaled), K (natural rows, kk-interleaved d)
__device__ uint2    g_v2 [BATCH*NHEADS*1024*64];     // V pairs: [b,h][t>>1][d] = (V[2i][d], V[2i+1][d])
__device__ unsigned g_att[MROWS*D_MODEL];            // flash out, old d-perm tf32
__device__ unsigned g_xt [MROWS*D_MODEL];            // X tf32, old d-perm
__device__ unsigned g_wqi[(D_MODEL/8*4)*(QKVCOLS*2)]; // w_qkv tf32, k-pair interleaved
__device__ unsigned g_wpi[(D_MODEL/8*4)*(D_MODEL*2)]; // w_proj tf32, k-pair interleaved
__device__ float g_cos[NTOK*HDIM];
__device__ float g_sin[NTOK*HDIM];
__device__ float g_xs [NTOK*HDIM];

// ---------------- helpers ----------------
__device__ __forceinline__ unsigned f2tf(float f) {
    unsigned u;
    asm("cvt.rna.tf32.f32 %0, %1;" : "=r"(u) : "f"(f));
    return u;
}
__device__ __forceinline__ void mma8(float c[4], const unsigned a[4], unsigned b0, unsigned b1) {
    asm("mma.sync.aligned.m16n8k8.row.col.f32.tf32.tf32.f32 "
        "{%0,%1,%2,%3},{%4,%5,%6,%7},{%8,%9},{%0,%1,%2,%3};"
        : "+f"(c[0]), "+f"(c[1]), "+f"(c[2]), "+f"(c[3])
        : "r"(a[0]), "r"(a[1]), "r"(a[2]), "r"(a[3]), "r"(b0), "r"(b1));
}
__device__ __forceinline__ void cpa16(unsigned dst, const void* src) {
    asm volatile("cp.async.cg.shared.global [%0], [%1], 16;" :: "r"(dst), "l"(src));
}
__device__ __forceinline__ void cpa_commit() {
    asm volatile("cp.async.commit_group;");
}
template<int N>
__device__ __forceinline__ void cpa_wait() {
    asm volatile("cp.async.wait_group %0;" :: "n"(N));
}

// ============================================================
// Kernel 1: xpos/ND-RoPE tables (fp64, matches numpy ref)
// ============================================================
__global__ void rope_tables_kernel() {
    int idx = blockIdx.x * blockDim.x + threadIdx.x;
    if (idx >= NTOK*HDIM) return;
    int n = idx >> 6;
    int d = idx & 63;
    int axis = d >> 5;
    int jj   = d & 31;
    int p    = jj >> 1;
    double t, half;
    if (axis == 0) { t = (double)(n >> 6); half = 16.0; }
    else           { t = (double)(n & 63); half = 32.0; }
    double inv_freq = pow(10000.0, -((double)(2*p)) / 32.0);
    double f  = t * inv_freq;
    double sbase = ((double)(2*p) + 0.4*32.0) / (1.4*32.0);
    double power = (t - half) / 64.0;
    double sc = pow(sbase, power);
    g_cos[idx] = (float)cos(f);
    g_sin[idx] = (float)sin(f);
    g_xs [idx] = (float)sc;
}

// ============================================================
// Kernel 1b: preconvert X (old d-perm) and weights (k-pair interleaved)
// ============================================================
__global__ void preconvert_kernel(const float* __restrict__ X,
                                  const float* __restrict__ Wq,
                                  const float* __restrict__ Wp) {
    const int NX  = MROWS*D_MODEL/4;
    const int NQ  = (D_MODEL/8*4)*(QKVCOLS/4);
    const int NP  = (D_MODEL/8*4)*(D_MODEL/4);
    int i = blockIdx.x * blockDim.x + threadIdx.x;
    if (i < NX) {
        float4 v = ((const float4*)X)[i];
        int e = i << 2;
        int off = (e & ~7) + ((e & 4) >> 2);
        g_xt[off+0] = f2tf(v.x);
        g_xt[off+2] = f2tf(v.y);
        g_xt[off+4] = f2tf(v.z);
        g_xt[off+6] = f2tf(v.w);
    } else if (i < NX + NQ) {
        int j = i - NX;
        int prow = j / (QKVCOLS/4);
        int cg   = (j - prow*(QKVCOLS/4)) << 2;
        int k    = ((prow >> 2) << 3) + (prow & 3);
        float4 v0 = *(const float4*)(Wq + (size_t)k*QKVCOLS + cg);
        float4 v1 = *(const float4*)(Wq + (size_t)(k+4)*QKVCOLS + cg);
        unsigned* d = &g_wqi[(size_t)prow*(QKVCOLS*2) + cg*2];
        uint4 u0; u0.x=f2tf(v0.x); u0.y=f2tf(v1.x); u0.z=f2tf(v0.y); u0.w=f2tf(v1.y);
        uint4 u1; u1.x=f2tf(v0.z); u1.y=f2tf(v1.z); u1.z=f2tf(v0.w); u1.w=f2tf(v1.w);
        *(uint4*)(d)   = u0;
        *(uint4*)(d+4) = u1;
    } else {
        int j = i - NX - NQ;
        if (j < NP) {
            int prow = j / (D_MODEL/4);
            int cg   = (j - prow*(D_MODEL/4)) << 2;
            int k    = ((prow >> 2) << 3) + (prow & 3);
            float4 v0 = *(const float4*)(Wp + (size_t)k*D_MODEL + cg);
            float4 v1 = *(const float4*)(Wp + (size_t)(k+4)*D_MODEL + cg);
            unsigned* d = &g_wpi[(size_t)prow*(D_MODEL*2) + cg*2];
            uint4 u0; u0.x=f2tf(v0.x); u0.y=f2tf(v1.x); u0.z=f2tf(v0.y); u0.w=f2tf(v1.y);
            uint4 u1; u1.x=f2tf(v0.z); u1.y=f2tf(v1.z); u1.z=f2tf(v0.w); u1.w=f2tf(v1.w);
            *(uint4*)(d)   = u0;
            *(uint4*)(d+4) = u1;
        }
    }
}

// ============================================================
// Kernel 2: TF32 GEMM, 2-stage cp.async; QKV epilogue writes
//   Q (old d-perm), K (natural rows, kk-interleaved d), V (t,t+1 pairs)
// ============================================================
#define AS_STR 40
#define BS_STR 264
#define GEMM_SMEM(TM) ((2*(TM)*AS_STR + 2*16*BS_STR)*4)

template<int NC, bool QKV, int TM>
__global__ __launch_bounds__(256, 2) void gemm_tf32_kernel(
    const float* __restrict__ bias, float* __restrict__ out)
{
    constexpr int MI = TM/32;
    extern __shared__ unsigned gsm_u[];
    unsigned* As = gsm_u;                    // [2][TM][AS_STR]
    unsigned* Bs = gsm_u + 2*TM*AS_STR;      // [2][16][BS_STR]

    const unsigned* Ap = QKV ? g_xt : g_att;
    const unsigned* Bp = QKV ? g_wqi : g_wpi;

    int tid = threadIdx.x;
    int lane = tid & 31, warp = tid >> 5;
    int lq = lane >> 2, lr = lane & 3;
    int wm = (warp >> 2) * (TM/2);
    int wn = (warp & 3) * 32;
    int bm = blockIdx.y * TM, bn = blockIdx.x * 128;

    float acc[MI][4][4];
#pragma unroll
    for (int mi = 0; mi < MI; mi++)
#pragma unroll
        for (int ni = 0; ni < 4; ni++)
#pragma unroll
            for (int r = 0; r < 4; r++) acc[mi][ni][r] = 0.f;

    int ar = tid >> 3, ac = (tid & 7) << 2;

    unsigned sA = (unsigned)__cvta_generic_to_shared(As);
    unsigned sB = (unsigned)__cvta_generic_to_shared(Bs);

    auto issue = [&](int stage, int k0) {
        unsigned dA = sA + (unsigned)(stage*TM*AS_STR)*4;
        unsigned dB = sB + (unsigned)(stage*16*BS_STR)*4;
#pragma unroll
        for (int p = 0; p < MI; p++)
            cpa16(dA + (unsigned)((ar + p*32)*AS_STR + ac)*4,
                  Ap + (size_t)(bm + ar + p*32)*1024 + k0 + ac);
#pragma unroll
        for (int p = 0; p < 4; p++) {
            int idx = p*256 + tid;
            int row = idx >> 6, c = (idx & 63) << 2;
            cpa16(dB + (unsigned)(row*BS_STR + c)*4,
                  Bp + (size_t)((k0>>1) + row)*(NC*2) + bn*2 + c);
        }
        cpa_commit();
    };

    issue(0, 0);
    issue(1, 32);

    const int NIT = 1024/32;
    for (int it = 0; it < NIT; it++) {
        int cur = it & 1;
        if (it + 2 < NIT) cpa_wait<1>(); else cpa_wait<0>();
        __syncthreads();

        const unsigned* Af = As + cur*TM*AS_STR;
        const unsigned* Bf = Bs + cur*16*BS_STR;
#pragma unroll
        for (int kk = 0; kk < 4; kk++) {
            unsigned af[MI][4];
            uint2 bf[4];
#pragma unroll
            for (int mi = 0; mi < MI; mi++) {
                int r = wm + mi*16 + lq;
                uint2 u0 = *(const uint2*)&Af[r*AS_STR + kk*8 + 2*lr];
                uint2 u1 = *(const uint2*)&Af[(r+8)*AS_STR + kk*8 + 2*lr];
                af[mi][0] = u0.x; af[mi][1] = u1.x;
                af[mi][2] = u0.y; af[mi][3] = u1.y;
            }
#pragma unroll
            for (int ni = 0; ni < 4; ni++)
                bf[ni] = *(const uint2*)&Bf[(kk*4 + lr)*BS_STR + (wn + ni*8 + lq)*2];
#pragma unroll
            for (int mi = 0; mi < MI; mi++)
#pragma unroll
                for (int ni = 0; ni < 4; ni++)
                    mma8(acc[mi][ni], af[mi], bf[ni].x, bf[ni].y);
        }
        __syncthreads();
        if (it + 2 < NIT) issue(cur, (it+2)*32);
    }

    // ---- epilogue ----
#pragma unroll
    for (int mi = 0; mi < MI; mi++) {
#pragma unroll
        for (int ni = 0; ni < 4; ni++) {
            int col = bn + wn + ni*8 + 2*lr;
            float bz0 = bias[col], bz1 = bias[col+1];
            int rA = bm + wm + mi*16 + lq;
            int rB = rA + 8;
            float a0 = acc[mi][ni][0] + bz0, a1 = acc[mi][ni][1] + bz1;
            float b0 = acc[mi][ni][2] + bz0, b1 = acc[mi][ni][3] + bz1;
            if (QKV) {
                int which = col >> 10, hh = (col >> 6) & 15, dd = col & 63;
                int bA = rA >> 11, nA = rA & 2047;
                int nB = nA + 8;   // same batch (16-aligned tiles)
                if (which < 2) {   // rotate q,k
                    int tiA = (nA << 6) + dd, tiB = (nB << 6) + dd;
                    float cA = g_cos[tiA], sA_ = g_sin[tiA], xA = g_xs[tiA];
                    float cB = g_cos[tiB], sB_ = g_sin[tiB], xB = g_xs[tiB];
                    float y0 = a0*cA - a1*sA_, y1 = a1*cA + a0*sA_;
                    float z0 = b0*cB - b1*sB_, z1 = b1*cB + b0*sB_;
                    if (which == 0) {   // Q: *xs, prescale 1/8, old d-perm
                        a0 = y0*xA*0.125f; a1 = y1*xA*0.125f;
                        b0 = z0*xB*0.125f; b1 = z1*xB*0.125f;
                        int p0 = (dd & ~7) + (((lr & 1) << 2) | (lr >> 1));
                        size_t qA = ((size_t)((0 + bA)*16 + hh)*2048 + nA)*64;
                        size_t qB = ((size_t)((0 + bA)*16 + hh)*2048 + nB)*64;
                        g_qkv[qA + p0]     = f2tf(a0);
                        g_qkv[qA + p0 + 2] = f2tf(a1);
                        g_qkv[qB + p0]     = f2tf(b0);
                        g_qkv[qB + p0 + 2] = f2tf(b1);
                    } else {            // K: /xs, NATURAL rows, kk-interleaved d
                        a0 = y0/xA; a1 = y1/xA; b0 = z0/xB; b1 = z1/xB;
                        int bb   = 16*(dd >> 4) + 2*((dd >> 3) & 1);
                        int off0 = bb + 8*(lr & 1) + (lr >> 1);
                        size_t kA = ((size_t)((2 + bA)*16 + hh)*2048 + nA)*64;
                        size_t kB = ((size_t)((2 + bA)*16 + hh)*2048 + nB)*64;
                        g_qkv[kA + off0]     = f2tf(a0);
                        g_qkv[kA + off0 + 4] = f2tf(a1);
                        g_qkv[kB + off0]     = f2tf(b0);
                        g_qkv[kB + off0 + 4] = f2tf(b1);
                    }
                } else {                // V: (t,t+1) pair layout, scalar stores
                    unsigned* vh = (unsigned*)(g_v2 + (size_t)(bA*16 + hh)*1024*64);
                    unsigned wA = (unsigned)((nA >> 1)*128 + dd*2 + (nA & 1));
                    unsigned wB = (unsigned)((nB >> 1)*128 + dd*2 + (nB & 1));
                    vh[wA]     = f2tf(a0);
                    vh[wA + 2] = f2tf(a1);
                    vh[wB]     = f2tf(b0);
                    vh[wB + 2] = f2tf(b1);
                }
            } else {
                *(float2*)&out[(size_t)rA*NC + col] = make_float2(a0, a1);
                *(float2*)&out[(size_t)rB*NC + col] = make_float2(b0, b1);
            }
        }
    }
}

// ============================================================
// Kernel 3: flash attention — 4 warps x 32 q-rows, dual m-tile,
//   LDS.128 K frags, P kept in registers (no smem roundtrip),
//   cp.async double-buffered K/V.
// ============================================================
#define KS_STR 80
#define VI_STR 136
#define FLASH_SMEM ((2*64*KS_STR + 2*32*VI_STR)*4)   // 75776

__global__ __launch_bounds__(128, 2) void flash_tf32_kernel() {
    extern __shared__ unsigned sm_u[];
    unsigned* Ks = sm_u;                 // [2][64][80]
    unsigned* Vi = sm_u + 2*64*KS_STR;   // [2][32][136]

    int tid = threadIdx.x;
    int lane = tid & 31, warp = tid >> 5;   // 4 warps
    int lq = lane >> 2, lr = lane & 3;
    int qt = blockIdx.x, bh = blockIdx.y;
    int b = bh >> 4, h = bh & 15;
    int r0 = warp * 32;

    const unsigned* Qg = g_qkv + ((size_t)((0 + b)*16 + h))*NTOK*HDIM + (size_t)qt*128*HDIM;
    const unsigned* Kg = g_qkv + ((size_t)((2 + b)*16 + h))*NTOK*HDIM;
    const unsigned* Vg = (const unsigned*)(g_v2 + (size_t)(b*16 + h)*1024*64);

    unsigned sKs = (unsigned)__cvta_generic_to_shared(Ks);
    unsigned sVi = (unsigned)__cvta_generic_to_shared(Vi);

    auto issueKV = [&](int kt, int s) {
        const unsigned* kg = Kg + (size_t)kt*64*HDIM;
        const unsigned* vg = Vg + (size_t)kt*32*128;
#pragma unroll
        for (int p = 0; p < 8; p++) {
            int idx = p*128 + tid;                     // 0..1023
            int krow = idx >> 4, kc = (idx & 15) << 2; // 64 rows x 16 chunks
            cpa16(sKs + (unsigned)((s*64 + krow)*KS_STR + kc)*4, kg + krow*64 + kc);
            int vrow = idx >> 5, vc = (idx & 31) << 2; // 32 rows x 32 chunks
            cpa16(sVi + (unsigned)((s*32 + vrow)*VI_STR + vc)*4, vg + vrow*128 + vc);
        }
        cpa_commit();
    };

    issueKV(0, 0);
    issueKV(1, 1);

    // Q fragments straight from gmem (old d-perm: logical (lr, lr+4) at 2lr, 2lr+1)
    unsigned qf[2][8][4];
#pragma unroll
    for (int mt = 0; mt < 2; mt++)
#pragma unroll
        for (int kk = 0; kk < 8; kk++) {
            uint2 u0 = *(const uint2*)(Qg + (size_t)(r0 + mt*16 + lq)*HDIM + kk*8 + 2*lr);
            uint2 u1 = *(const uint2*)(Qg + (size_t)(r0 + mt*16 + lq + 8)*HDIM + kk*8 + 2*lr);
            qf[mt][kk][0] = u0.x; qf[mt][kk][1] = u1.x;
            qf[mt][kk][2] = u0.y; qf[mt][kk][3] = u1.y;
        }

    float O[2][8][4];
    float mst[4] = {-1e30f, -1e30f, -1e30f, -1e30f};
    float lst[4] = {0.f, 0.f, 0.f, 0.f};
#pragma unroll
    for (int mt = 0; mt < 2; mt++)
#pragma unroll
        for (int n = 0; n < 8; n++)
#pragma unroll
            for (int r = 0; r < 4; r++) O[mt][n][r] = 0.f;

    int pp = ((lr & 1) << 2) | (lr >> 1);   // old d-perm pos of logical 2lr (epilogue)

    const int NKT = NTOK/64;
    for (int kt = 0; kt < NKT; kt++) {
        int s = kt & 1;
        if (kt + 2 < NKT) cpa_wait<1>(); else cpa_wait<0>();
        __syncthreads();

        const unsigned* Kf = Ks + s*64*KS_STR;
        const unsigned* Vf = Vi + s*32*VI_STR;

        // ---- S = Q K^T, both m-tiles per K fragment ----
        float s0[8][4], s1[8][4];
#pragma unroll
        for (int n = 0; n < 8; n++) {
            s0[n][0]=s0[n][1]=s0[n][2]=s0[n][3]=0.f;
            s1[n][0]=s1[n][1]=s1[n][2]=s1[n][3]=0.f;
            const unsigned* krow = &Kf[(n*8 + lq)*KS_STR + 4*lr];
#pragma unroll
            for (int kkp = 0; kkp < 4; kkp++) {
                uint4 kb = *(const uint4*)(krow + kkp*16);
                mma8(s0[n], qf[0][2*kkp],   kb.x, kb.y);
                mma8(s0[n], qf[0][2*kkp+1], kb.z, kb.w);
                mma8(s1[n], qf[1][2*kkp],   kb.x, kb.y);
                mma8(s1[n], qf[1][2*kkp+1], kb.z, kb.w);
            }
        }

        // ---- online softmax: 4 row-groups; exps kept in s0/s1 regs ----
        float mA=-1e30f, mB=-1e30f, mC=-1e30f, mD=-1e30f;
#pragma unroll
        for (int n = 0; n < 8; n++) {
            mA = fmaxf(mA, fmaxf(s0[n][0], s0[n][1]));
            mB = fmaxf(mB, fmaxf(s0[n][2], s0[n][3]));
            mC = fmaxf(mC, fmaxf(s1[n][0], s1[n][1]));
            mD = fmaxf(mD, fmaxf(s1[n][2], s1[n][3]));
        }
        mA = fmaxf(mA, __shfl_xor_sync(0xffffffffu, mA, 1));
        mA = fmaxf(mA, __shfl_xor_sync(0xffffffffu, mA, 2));
        mB = fmaxf(mB, __shfl_xor_sync(0xffffffffu, mB, 1));
        mB = fmaxf(mB, __shfl_xor_sync(0xffffffffu, mB, 2));
        mC = fmaxf(mC, __shfl_xor_sync(0xffffffffu, mC, 1));
        mC = fmaxf(mC, __shfl_xor_sync(0xffffffffu, mC, 2));
        mD = fmaxf(mD, __shfl_xor_sync(0xffffffffu, mD, 1));
        mD = fmaxf(mD, __shfl_xor_sync(0xffffffffu, mD, 2));
        float mnA = fmaxf(mst[0], mA), mnB = fmaxf(mst[1], mB);
        float mnC = fmaxf(mst[2], mC), mnD = fmaxf(mst[3], mD);
        float cA = __expf(mst[0]-mnA), cB = __expf(mst[1]-mnB);
        float cC = __expf(mst[2]-mnC), cD = __expf(mst[3]-mnD);
        float sA=0.f, sB=0.f, sC=0.f, sD=0.f;
#pragma unroll
        for (int n = 0; n < 8; n++) {
            s0[n][0] = __expf(s0[n][0]-mnA); s0[n][1] = __expf(s0[n][1]-mnA);
            s0[n][2] = __expf(s0[n][2]-mnB); s0[n][3] = __expf(s0[n][3]-mnB);
            s1[n][0] = __expf(s1[n][0]-mnC); s1[n][1] = __expf(s1[n][1]-mnC);
            s1[n][2] = __expf(s1[n][2]-mnD); s1[n][3] = __expf(s1[n][3]-mnD);
            sA += s0[n][0]+s0[n][1]; sB += s0[n][2]+s0[n][3];
            sC += s1[n][0]+s1[n][1]; sD += s1[n][2]+s1[n][3];
        }
        sA += __shfl_xor_sync(0xffffffffu, sA, 1);
        sA += __shfl_xor_sync(0xffffffffu, sA, 2);
        sB += __shfl_xor_sync(0xffffffffu, sB, 1);
        sB += __shfl_xor_sync(0xffffffffu, sB, 2);
        sC += __shfl_xor_sync(0xffffffffu, sC, 1);
        sC += __shfl_xor_sync(0xffffffffu, sC, 2);
        sD += __shfl_xor_sync(0xffffffffu, sD, 1);
        sD += __shfl_xor_sync(0xffffffffu, sD, 2);
        lst[0] = lst[0]*cA + sA; mst[0] = mnA;
        lst[1] = lst[1]*cB + sB; mst[1] = mnB;
        lst[2] = lst[2]*cC + sC; mst[2] = mnC;
        lst[3] = lst[3]*cD + sD; mst[3] = mnD;
#pragma unroll
        for (int n = 0; n < 8; n++) {
            O[0][n][0] *= cA; O[0][n][1] *= cA;
            O[0][n][2] *= cB; O[0][n][3] *= cB;
            O[1][n][0] *= cC; O[1][n][1] *= cC;
            O[1][n][2] *= cD; O[1][n][3] *= cD;
        }

        // ---- O += P V : P A-frags direct from registers ----
        // k-pos lr <-> token 8kk+2lr (V pair .x), k-pos lr+4 <-> 8kk+2lr+1 (.y)
#pragma unroll
        for (int kk = 0; kk < 8; kk++) {
            unsigned pa0[4], pa1[4];
            pa0[0] = f2tf(s0[kk][0]); pa0[1] = f2tf(s0[kk][2]);
            pa0[2] = f2tf(s0[kk][1]); pa0[3] = f2tf(s0[kk][3]);
            pa1[0] = f2tf(s1[kk][0]); pa1[1] = f2tf(s1[kk][2]);
            pa1[2] = f2tf(s1[kk][1]); pa1[3] = f2tf(s1[kk][3]);
            const unsigned* vrow = &Vf[(kk*4 + lr)*VI_STR];
#pragma unroll
            for (int n = 0; n < 8; n++) {
                uint2 vb = *(const uint2*)(vrow + (n*8 + lq)*2);
                mma8(O[0][n], pa0, vb.x, vb.y);
                mma8(O[1][n], pa1, vb.x, vb.y);
            }
        }

        __syncthreads();
        if (kt + 2 < NKT) issueKV(kt + 2, s);
    }

    // epilogue: normalize, tf32-round, old-perm store into g_att
    float iA = 1.f/lst[0], iB = 1.f/lst[1], iC = 1.f/lst[2], iD = 1.f/lst[3];
    int rowA = qt*128 + r0 + lq;
#pragma unroll
    for (int n = 0; n < 8; n++) {
        int col = h*HDIM + n*8 + pp;
        size_t b0 = (size_t)(b*NTOK + rowA)*D_MODEL + col;
        size_t b1 = (size_t)(b*NTOK + rowA + 8)*D_MODEL + col;
        size_t b2 = (size_t)(b*NTOK + rowA + 16)*D_MODEL + col;
        size_t b3 = (size_t)(b*NTOK + rowA + 24)*D_MODEL + col;
        g_att[b0]     = f2tf(O[0][n][0]*iA);
        g_att[b0 + 2] = f2tf(O[0][n][1]*iA);
        g_att[b1]     = f2tf(O[0][n][2]*iB);
        g_att[b1 + 2] = f2tf(O[0][n][3]*iB);
        g_att[b2]     = f2tf(O[1][n][0]*iC);
        g_att[b2 + 2] = f2tf(O[1][n][1]*iC);
        g_att[b3]     = f2tf(O[1][n][2]*iD);
        g_att[b3 + 2] = f2tf(O[1][n][3]*iD);
    }
}

// ============================================================
// launch
// ============================================================
extern "C" void kernel_launch(void* const* d_in, const int* in_sizes, int n_in,
                              void* d_out, int out_size) {
    const float* x      = (const float*)d_in[0];
    const float* w_qkv  = (const float*)d_in[1];
    const float* b_qkv  = (const float*)d_in[2];
    const float* w_proj = (const float*)d_in[3];
    const float* b_proj = (const float*)d_in[4];
    float* out = (float*)d_out;
    (void)in_sizes; (void)n_in; (void)out_size;

    rope_tables_kernel<<<(NTOK*HDIM)/256, 256>>>();

    const int NCONV = MROWS*D_MODEL/4 + (D_MODEL/8*4)*(QKVCOLS/4) + (D_MODEL/8*4)*(D_MODEL/4);
    preconvert_kernel<<<(NCONV + 255)/256, 256>>>(x, w_qkv, w_proj);

    cudaFuncSetAttribute(gemm_tf32_kernel<QKVCOLS, true, 128>,
                         cudaFuncAttributeMaxDynamicSharedMemorySize, GEMM_SMEM(128));
    gemm_tf32_kernel<QKVCOLS, true, 128>
        <<<dim3(QKVCOLS/128, MROWS/128), 256, GEMM_SMEM(128)>>>(b_qkv, nullptr);

    cudaFuncSetAttribute(flash_tf32_kernel,
                         cudaFuncAttributeMaxDynamicSharedMemorySize, FLASH_SMEM);
    flash_tf32_kernel<<<dim3(NTOK/128, BATCH*NHEADS), 128, FLASH_SMEM>>>();

    cudaFuncSetAttribute(gemm_tf32_kernel<D_MODEL, false, 64>,
                         cudaFuncAttributeMaxDynamicSharedMemorySize, GEMM_SMEM(64));
    gemm_tf32_kernel<D_MODEL, false, 64>
        <<<dim3(D_MODEL/128, MROWS/64), 256, GEMM_SMEM(64)>>>(b_proj, out);
}

// round 10
// speedup vs baseline: 1.4376x; 1.0203x over previous
#include <cuda_runtime.h>
#include <math.h>

// ---------------- problem constants ----------------
#define D_MODEL  1024
#define NHEADS   16
#define HDIM     64
#define NTOK     2048
#define BATCH    2
#define MROWS    (BATCH*NTOK)       // 4096
#define QKVCOLS  (3*D_MODEL)        // 3072

// Q prescale: (1/8) * log2(e)  — scores land in log2 domain
#define QSCALE 0.18033688011112042f

// ---------------- scratch (tf32 bit patterns) ----------------
__device__ unsigned g_qkv[3*BATCH*NHEADS*NTOK*HDIM]; // Q (natural rows, d-perm, prescaled), K (natural rows, kk-interleaved d)
__device__ uint2    g_v2 [BATCH*NHEADS*1024*64];     // V pairs: [b,h][t>>1][d] = (V[2i][d], V[2i+1][d])
__device__ unsigned g_att[MROWS*D_MODEL];            // flash out, d-perm tf32
__device__ unsigned g_xt [MROWS*D_MODEL];            // X tf32, d-perm
__device__ unsigned g_wqi[(D_MODEL/8*4)*(QKVCOLS*2)]; // w_qkv tf32, k-pair interleaved
__device__ unsigned g_wpi[(D_MODEL/8*4)*(D_MODEL*2)]; // w_proj tf32, k-pair interleaved
__device__ float g_cos[NTOK*HDIM];
__device__ float g_sin[NTOK*HDIM];
__device__ float g_xs [NTOK*HDIM];

// ---------------- helpers ----------------
__device__ __forceinline__ unsigned f2tf(float f) {
    unsigned u;
    asm("cvt.rna.tf32.f32 %0, %1;" : "=r"(u) : "f"(f));
    return u;
}
__device__ __forceinline__ void mma8(float c[4], const unsigned a[4], unsigned b0, unsigned b1) {
    asm("mma.sync.aligned.m16n8k8.row.col.f32.tf32.tf32.f32 "
        "{%0,%1,%2,%3},{%4,%5,%6,%7},{%8,%9},{%0,%1,%2,%3};"
        : "+f"(c[0]), "+f"(c[1]), "+f"(c[2]), "+f"(c[3])
        : "r"(a[0]), "r"(a[1]), "r"(a[2]), "r"(a[3]), "r"(b0), "r"(b1));
}
__device__ __forceinline__ void cpa16(unsigned dst, const void* src) {
    asm volatile("cp.async.cg.shared.global [%0], [%1], 16;" :: "r"(dst), "l"(src));
}
__device__ __forceinline__ void cpa_commit() {
    asm volatile("cp.async.commit_group;");
}
template<int N>
__device__ __forceinline__ void cpa_wait() {
    asm volatile("cp.async.wait_group %0;" :: "n"(N));
}

// ============================================================
// Kernel 1: xpos/ND-RoPE tables (fp64, matches numpy ref)
// ============================================================
__global__ void rope_tables_kernel() {
    int idx = blockIdx.x * blockDim.x + threadIdx.x;
    if (idx >= NTOK*HDIM) return;
    int n = idx >> 6;
    int d = idx & 63;
    int axis = d >> 5;
    int jj   = d & 31;
    int p    = jj >> 1;
    double t, half;
    if (axis == 0) { t = (double)(n >> 6); half = 16.0; }
    else           { t = (double)(n & 63); half = 32.0; }
    double inv_freq = pow(10000.0, -((double)(2*p)) / 32.0);
    double f  = t * inv_freq;
    double sbase = ((double)(2*p) + 0.4*32.0) / (1.4*32.0);
    double power = (t - half) / 64.0;
    double sc = pow(sbase, power);
    g_cos[idx] = (float)cos(f);
    g_sin[idx] = (float)sin(f);
    g_xs [idx] = (float)sc;
}

// ============================================================
// Kernel 1b: preconvert X (d-perm) and weights (k-pair interleaved)
// ============================================================
__global__ void preconvert_kernel(const float* __restrict__ X,
                                  const float* __restrict__ Wq,
                                  const float* __restrict__ Wp) {
    const int NX  = MROWS*D_MODEL/4;
    const int NQ  = (D_MODEL/8*4)*(QKVCOLS/4);
    const int NP  = (D_MODEL/8*4)*(D_MODEL/4);
    int i = blockIdx.x * blockDim.x + threadIdx.x;
    if (i < NX) {
        float4 v = ((const float4*)X)[i];
        int e = i << 2;
        int off = (e & ~7) + ((e & 4) >> 2);
        g_xt[off+0] = f2tf(v.x);
        g_xt[off+2] = f2tf(v.y);
        g_xt[off+4] = f2tf(v.z);
        g_xt[off+6] = f2tf(v.w);
    } else if (i < NX + NQ) {
        int j = i - NX;
        int prow = j / (QKVCOLS/4);
        int cg   = (j - prow*(QKVCOLS/4)) << 2;
        int k    = ((prow >> 2) << 3) + (prow & 3);
        float4 v0 = *(const float4*)(Wq + (size_t)k*QKVCOLS + cg);
        float4 v1 = *(const float4*)(Wq + (size_t)(k+4)*QKVCOLS + cg);
        unsigned* d = &g_wqi[(size_t)prow*(QKVCOLS*2) + cg*2];
        uint4 u0; u0.x=f2tf(v0.x); u0.y=f2tf(v1.x); u0.z=f2tf(v0.y); u0.w=f2tf(v1.y);
        uint4 u1; u1.x=f2tf(v0.z); u1.y=f2tf(v1.z); u1.z=f2tf(v0.w); u1.w=f2tf(v1.w);
        *(uint4*)(d)   = u0;
        *(uint4*)(d+4) = u1;
    } else {
        int j = i - NX - NQ;
        if (j < NP) {
            int prow = j / (D_MODEL/4);
            int cg   = (j - prow*(D_MODEL/4)) << 2;
            int k    = ((prow >> 2) << 3) + (prow & 3);
            float4 v0 = *(const float4*)(Wp + (size_t)k*D_MODEL + cg);
            float4 v1 = *(const float4*)(Wp + (size_t)(k+4)*D_MODEL + cg);
            unsigned* d = &g_wpi[(size_t)prow*(D_MODEL*2) + cg*2];
            uint4 u0; u0.x=f2tf(v0.x); u0.y=f2tf(v1.x); u0.z=f2tf(v0.y); u0.w=f2tf(v1.y);
            uint4 u1; u1.x=f2tf(v0.z); u1.y=f2tf(v1.z); u1.z=f2tf(v0.w); u1.w=f2tf(v1.w);
            *(uint4*)(d)   = u0;
            *(uint4*)(d+4) = u1;
        }
    }
}

// ============================================================
// Kernel 2: TF32 GEMM, 3-stage cp.async, ONE barrier per k-iter
// ============================================================
#define AS_STR 40
#define BS_STR 264
#define GEMM_SMEM(TM) ((3*(TM)*AS_STR + 3*16*BS_STR)*4)

template<int NC, bool QKV, int TM>
__global__ __launch_bounds__(256, 2) void gemm_tf32_kernel(
    const float* __restrict__ bias, float* __restrict__ out)
{
    constexpr int MI = TM/32;
    extern __shared__ unsigned gsm_u[];
    unsigned* As = gsm_u;                    // [3][TM][AS_STR]
    unsigned* Bs = gsm_u + 3*TM*AS_STR;      // [3][16][BS_STR]

    const unsigned* Ap = QKV ? g_xt : g_att;
    const unsigned* Bp = QKV ? g_wqi : g_wpi;

    int tid = threadIdx.x;
    int lane = tid & 31, warp = tid >> 5;
    int lq = lane >> 2, lr = lane & 3;
    int wm = (warp >> 2) * (TM/2);
    int wn = (warp & 3) * 32;
    int bm = blockIdx.y * TM, bn = blockIdx.x * 128;

    float acc[MI][4][4];
#pragma unroll
    for (int mi = 0; mi < MI; mi++)
#pragma unroll
        for (int ni = 0; ni < 4; ni++)
#pragma unroll
            for (int r = 0; r < 4; r++) acc[mi][ni][r] = 0.f;

    int ar = tid >> 3, ac = (tid & 7) << 2;

    unsigned sA = (unsigned)__cvta_generic_to_shared(As);
    unsigned sB = (unsigned)__cvta_generic_to_shared(Bs);

    auto issue = [&](int stage, int k0) {
        unsigned dA = sA + (unsigned)(stage*TM*AS_STR)*4;
        unsigned dB = sB + (unsigned)(stage*16*BS_STR)*4;
#pragma unroll
        for (int p = 0; p < MI; p++)
            cpa16(dA + (unsigned)((ar + p*32)*AS_STR + ac)*4,
                  Ap + (size_t)(bm + ar + p*32)*1024 + k0 + ac);
#pragma unroll
        for (int p = 0; p < 4; p++) {
            int idx = p*256 + tid;
            int row = idx >> 6, c = (idx & 63) << 2;
            cpa16(dB + (unsigned)(row*BS_STR + c)*4,
                  Bp + (size_t)((k0>>1) + row)*(NC*2) + bn*2 + c);
        }
        cpa_commit();
    };

    issue(0, 0);
    issue(1, 32);

    const int NIT = 1024/32;
    int cur = 0;
    for (int it = 0; it < NIT; it++) {
        if (it < NIT-1) cpa_wait<1>(); else cpa_wait<0>();
        __syncthreads();
        // issue into the slot computed at it-1 (all warps past it via the sync)
        if (it + 2 < NIT) {
            int nxt = cur + 2; if (nxt >= 3) nxt -= 3;
            issue(nxt, (it+2)*32);
        }

        const unsigned* Af = As + cur*TM*AS_STR;
        const unsigned* Bf = Bs + cur*16*BS_STR;
#pragma unroll
        for (int kk = 0; kk < 4; kk++) {
            unsigned af[MI][4];
            uint2 bf[4];
#pragma unroll
            for (int mi = 0; mi < MI; mi++) {
                int r = wm + mi*16 + lq;
                uint2 u0 = *(const uint2*)&Af[r*AS_STR + kk*8 + 2*lr];
                uint2 u1 = *(const uint2*)&Af[(r+8)*AS_STR + kk*8 + 2*lr];
                af[mi][0] = u0.x; af[mi][1] = u1.x;
                af[mi][2] = u0.y; af[mi][3] = u1.y;
            }
#pragma unroll
            for (int ni = 0; ni < 4; ni++)
                bf[ni] = *(const uint2*)&Bf[(kk*4 + lr)*BS_STR + (wn + ni*8 + lq)*2];
#pragma unroll
            for (int mi = 0; mi < MI; mi++)
#pragma unroll
                for (int ni = 0; ni < 4; ni++)
                    mma8(acc[mi][ni], af[mi], bf[ni].x, bf[ni].y);
        }
        if (++cur == 3) cur = 0;
    }

    // ---- epilogue ----
#pragma unroll
    for (int mi = 0; mi < MI; mi++) {
#pragma unroll
        for (int ni = 0; ni < 4; ni++) {
            int col = bn + wn + ni*8 + 2*lr;
            float bz0 = bias[col], bz1 = bias[col+1];
            int rA = bm + wm + mi*16 + lq;
            int rB = rA + 8;
            float a0 = acc[mi][ni][0] + bz0, a1 = acc[mi][ni][1] + bz1;
            float b0 = acc[mi][ni][2] + bz0, b1 = acc[mi][ni][3] + bz1;
            if (QKV) {
                int which = col >> 10, hh = (col >> 6) & 15, dd = col & 63;
                int bA = rA >> 11, nA = rA & 2047;
                int nB = nA + 8;
                if (which < 2) {   // rotate q,k
                    int tiA = (nA << 6) + dd, tiB = (nB << 6) + dd;
                    float cA = g_cos[tiA], sA_ = g_sin[tiA], xA = g_xs[tiA];
                    float cB = g_cos[tiB], sB_ = g_sin[tiB], xB = g_xs[tiB];
                    float y0 = a0*cA - a1*sA_, y1 = a1*cA + a0*sA_;
                    float z0 = b0*cB - b1*sB_, z1 = b1*cB + b0*sB_;
                    if (which == 0) {   // Q: *xs, prescale (1/8)*log2e, d-perm
                        a0 = y0*xA*QSCALE; a1 = y1*xA*QSCALE;
                        b0 = z0*xB*QSCALE; b1 = z1*xB*QSCALE;
                        int p0 = (dd & ~7) + (((lr & 1) << 2) | (lr >> 1));
                        size_t qA = ((size_t)((0 + bA)*16 + hh)*2048 + nA)*64;
                        size_t qB = ((size_t)((0 + bA)*16 + hh)*2048 + nB)*64;
                        g_qkv[qA + p0]     = f2tf(a0);
                        g_qkv[qA + p0 + 2] = f2tf(a1);
                        g_qkv[qB + p0]     = f2tf(b0);
                        g_qkv[qB + p0 + 2] = f2tf(b1);
                    } else {            // K: /xs, natural rows, kk-interleaved d
                        a0 = y0/xA; a1 = y1/xA; b0 = z0/xB; b1 = z1/xB;
                        int bb   = 16*(dd >> 4) + 2*((dd >> 3) & 1);
                        int off0 = bb + 8*(lr & 1) + (lr >> 1);
                        size_t kA = ((size_t)((2 + bA)*16 + hh)*2048 + nA)*64;
                        size_t kB = ((size_t)((2 + bA)*16 + hh)*2048 + nB)*64;
                        g_qkv[kA + off0]     = f2tf(a0);
                        g_qkv[kA + off0 + 4] = f2tf(a1);
                        g_qkv[kB + off0]     = f2tf(b0);
                        g_qkv[kB + off0 + 4] = f2tf(b1);
                    }
                } else {                // V: (t,t+1) pair layout, scalar stores
                    unsigned* vh = (unsigned*)(g_v2 + (size_t)(bA*16 + hh)*1024*64);
                    unsigned wA = (unsigned)((nA >> 1)*128 + dd*2 + (nA & 1));
                    unsigned wB = (unsigned)((nB >> 1)*128 + dd*2 + (nB & 1));
                    vh[wA]     = f2tf(a0);
                    vh[wA + 2] = f2tf(a1);
                    vh[wB]     = f2tf(b0);
                    vh[wB + 2] = f2tf(b1);
                }
            } else {
                *(float2*)&out[(size_t)rA*NC + col] = make_float2(a0, a1);
                *(float2*)&out[(size_t)rB*NC + col] = make_float2(b0, b1);
            }
        }
    }
}

// ============================================================
// Kernel 3: flash attention — 4 warps x 32 q-rows, dual m-tile,
//   LDS.128 K frags, P in registers, exp2-domain softmax,
//   cp.async double-buffered K/V.
// ============================================================
#define KS_STR 80
#define VI_STR 136
#define FLASH_SMEM ((2*64*KS_STR + 2*32*VI_STR)*4)   // 75776

__global__ __launch_bounds__(128, 2) void flash_tf32_kernel() {
    extern __shared__ unsigned sm_u[];
    unsigned* Ks = sm_u;                 // [2][64][80]
    unsigned* Vi = sm_u + 2*64*KS_STR;   // [2][32][136]

    int tid = threadIdx.x;
    int lane = tid & 31, warp = tid >> 5;   // 4 warps
    int lq = lane >> 2, lr = lane & 3;
    int qt = blockIdx.x, bh = blockIdx.y;
    int b = bh >> 4, h = bh & 15;
    int r0 = warp * 32;

    const unsigned* Qg = g_qkv + ((size_t)((0 + b)*16 + h))*NTOK*HDIM + (size_t)qt*128*HDIM;
    const unsigned* Kg = g_qkv + ((size_t)((2 + b)*16 + h))*NTOK*HDIM;
    const unsigned* Vg = (const unsigned*)(g_v2 + (size_t)(b*16 + h)*1024*64);

    unsigned sKs = (unsigned)__cvta_generic_to_shared(Ks);
    unsigned sVi = (unsigned)__cvta_generic_to_shared(Vi);

    auto issueKV = [&](int kt, int s) {
        const unsigned* kg = Kg + (size_t)kt*64*HDIM;
        const unsigned* vg = Vg + (size_t)kt*32*128;
#pragma unroll
        for (int p = 0; p < 8; p++) {
            int idx = p*128 + tid;
            int krow = idx >> 4, kc = (idx & 15) << 2;
            cpa16(sKs + (unsigned)((s*64 + krow)*KS_STR + kc)*4, kg + krow*64 + kc);
            int vrow = idx >> 5, vc = (idx & 31) << 2;
            cpa16(sVi + (unsigned)((s*32 + vrow)*VI_STR + vc)*4, vg + vrow*128 + vc);
        }
        cpa_commit();
    };

    issueKV(0, 0);
    issueKV(1, 1);

    // Q fragments straight from gmem
    unsigned qf[2][8][4];
#pragma unroll
    for (int mt = 0; mt < 2; mt++)
#pragma unroll
        for (int kk = 0; kk < 8; kk++) {
            uint2 u0 = *(const uint2*)(Qg + (size_t)(r0 + mt*16 + lq)*HDIM + kk*8 + 2*lr);
            uint2 u1 = *(const uint2*)(Qg + (size_t)(r0 + mt*16 + lq + 8)*HDIM + kk*8 + 2*lr);
            qf[mt][kk][0] = u0.x; qf[mt][kk][1] = u1.x;
            qf[mt][kk][2] = u0.y; qf[mt][kk][3] = u1.y;
        }

    float O[2][8][4];
    float mst[4] = {-1e30f, -1e30f, -1e30f, -1e30f};
    float lst[4] = {0.f, 0.f, 0.f, 0.f};
#pragma unroll
    for (int mt = 0; mt < 2; mt++)
#pragma unroll
        for (int n = 0; n < 8; n++)
#pragma unroll
            for (int r = 0; r < 4; r++) O[mt][n][r] = 0.f;

    int pp = ((lr & 1) << 2) | (lr >> 1);

    const int NKT = NTOK/64;
    for (int kt = 0; kt < NKT; kt++) {
        int s = kt & 1;
        if (kt + 2 < NKT) cpa_wait<1>(); else cpa_wait<0>();
        __syncthreads();

        const unsigned* Kf = Ks + s*64*KS_STR;
        const unsigned* Vf = Vi + s*32*VI_STR;

        // ---- S = Q K^T (log2-domain scores), both m-tiles ----
        float s0[8][4], s1[8][4];
#pragma unroll
        for (int n = 0; n < 8; n++) {
            s0[n][0]=s0[n][1]=s0[n][2]=s0[n][3]=0.f;
            s1[n][0]=s1[n][1]=s1[n][2]=s1[n][3]=0.f;
            const unsigned* krow = &Kf[(n*8 + lq)*KS_STR + 4*lr];
#pragma unroll
            for (int kkp = 0; kkp < 4; kkp++) {
                uint4 kb = *(const uint4*)(krow + kkp*16);
                mma8(s0[n], qf[0][2*kkp],   kb.x, kb.y);
                mma8(s0[n], qf[0][2*kkp+1], kb.z, kb.w);
                mma8(s1[n], qf[1][2*kkp],   kb.x, kb.y);
                mma8(s1[n], qf[1][2*kkp+1], kb.z, kb.w);
            }
        }

        // ---- online softmax in exp2 domain ----
        float mA=-1e30f, mB=-1e30f, mC=-1e30f, mD=-1e30f;
#pragma unroll
        for (int n = 0; n < 8; n++) {
            mA = fmaxf(mA, fmaxf(s0[n][0], s0[n][1]));
            mB = fmaxf(mB, fmaxf(s0[n][2], s0[n][3]));
            mC = fmaxf(mC, fmaxf(s1[n][0], s1[n][1]));
            mD = fmaxf(mD, fmaxf(s1[n][2], s1[n][3]));
        }
        mA = fmaxf(mA, __shfl_xor_sync(0xffffffffu, mA, 1));
        mA = fmaxf(mA, __shfl_xor_sync(0xffffffffu, mA, 2));
        mB = fmaxf(mB, __shfl_xor_sync(0xffffffffu, mB, 1));
        mB = fmaxf(mB, __shfl_xor_sync(0xffffffffu, mB, 2));
        mC = fmaxf(mC, __shfl_xor_sync(0xffffffffu, mC, 1));
        mC = fmaxf(mC, __shfl_xor_sync(0xffffffffu, mC, 2));
        mD = fmaxf(mD, __shfl_xor_sync(0xffffffffu, mD, 1));
        mD = fmaxf(mD, __shfl_xor_sync(0xffffffffu, mD, 2));
        float mnA = fmaxf(mst[0], mA), mnB = fmaxf(mst[1], mB);
        float mnC = fmaxf(mst[2], mC), mnD = fmaxf(mst[3], mD);
        float cA = exp2f(mst[0]-mnA), cB = exp2f(mst[1]-mnB);
        float cC = exp2f(mst[2]-mnC), cD = exp2f(mst[3]-mnD);
        float sA=0.f, sB=0.f, sC=0.f, sD=0.f;
#pragma unroll
        for (int n = 0; n < 8; n++) {
            s0[n][0] = exp2f(s0[n][0]-mnA); s0[n][1] = exp2f(s0[n][1]-mnA);
            s0[n][2] = exp2f(s0[n][2]-mnB); s0[n][3] = exp2f(s0[n][3]-mnB);
            s1[n][0] = exp2f(s1[n][0]-mnC); s1[n][1] = exp2f(s1[n][1]-mnC);
            s1[n][2] = exp2f(s1[n][2]-mnD); s1[n][3] = exp2f(s1[n][3]-mnD);
            sA += s0[n][0]+s0[n][1]; sB += s0[n][2]+s0[n][3];
            sC += s1[n][0]+s1[n][1]; sD += s1[n][2]+s1[n][3];
        }
        sA += __shfl_xor_sync(0xffffffffu, sA, 1);
        sA += __shfl_xor_sync(0xffffffffu, sA, 2);
        sB += __shfl_xor_sync(0xffffffffu, sB, 1);
        sB += __shfl_xor_sync(0xffffffffu, sB, 2);
        sC += __shfl_xor_sync(0xffffffffu, sC, 1);
        sC += __shfl_xor_sync(0xffffffffu, sC, 2);
        sD += __shfl_xor_sync(0xffffffffu, sD, 1);
        sD += __shfl_xor_sync(0xffffffffu, sD, 2);
        lst[0] = lst[0]*cA + sA; mst[0] = mnA;
        lst[1] = lst[1]*cB + sB; mst[1] = mnB;
        lst[2] = lst[2]*cC + sC; mst[2] = mnC;
        lst[3] = lst[3]*cD + sD; mst[3] = mnD;
#pragma unroll
        for (int n = 0; n < 8; n++) {
            O[0][n][0] *= cA; O[0][n][1] *= cA;
            O[0][n][2] *= cB; O[0][n][3] *= cB;
            O[1][n][0] *= cC; O[1][n][1] *= cC;
            O[1][n][2] *= cD; O[1][n][3] *= cD;
        }

        // ---- O += P V : P A-frags direct from registers ----
#pragma unroll
        for (int kk = 0; kk < 8; kk++) {
            unsigned pa0[4], pa1[4];
            pa0[0] = f2tf(s0[kk][0]); pa0[1] = f2tf(s0[kk][2]);
            pa0[2] = f2tf(s0[kk][1]); pa0[3] = f2tf(s0[kk][3]);
            pa1[0] = f2tf(s1[kk][0]); pa1[1] = f2tf(s1[kk][2]);
            pa1[2] = f2tf(s1[kk][1]); pa1[3] = f2tf(s1[kk][3]);
            const unsigned* vrow = &Vf[(kk*4 + lr)*VI_STR];
#pragma unroll
            for (int n = 0; n < 8; n++) {
                uint2 vb = *(const uint2*)(vrow + (n*8 + lq)*2);
                mma8(O[0][n], pa0, vb.x, vb.y);
                mma8(O[1][n], pa1, vb.x, vb.y);
            }
        }

        __syncthreads();
        if (kt + 2 < NKT) issueKV(kt + 2, s);
    }

    // epilogue: normalize, tf32-round, d-perm store into g_att
    float iA = 1.f/lst[0], iB = 1.f/lst[1], iC = 1.f/lst[2], iD = 1.f/lst[3];
    int rowA = qt*128 + r0 + lq;
#pragma unroll
    for (int n = 0; n < 8; n++) {
        int col = h*HDIM + n*8 + pp;
        size_t b0 = (size_t)(b*NTOK + rowA)*D_MODEL + col;
        size_t b1 = (size_t)(b*NTOK + rowA + 8)*D_MODEL + col;
        size_t b2 = (size_t)(b*NTOK + rowA + 16)*D_MODEL + col;
        size_t b3 = (size_t)(b*NTOK + rowA + 24)*D_MODEL + col;
        g_att[b0]     = f2tf(O[0][n][0]*iA);
        g_att[b0 + 2] = f2tf(O[0][n][1]*iA);
        g_att[b1]     = f2tf(O[0][n][2]*iB);
        g_att[b1 + 2] = f2tf(O[0][n][3]*iB);
        g_att[b2]     = f2tf(O[1][n][0]*iC);
        g_att[b2 + 2] = f2tf(O[1][n][1]*iC);
        g_att[b3]     = f2tf(O[1][n][2]*iD);
        g_att[b3 + 2] = f2tf(O[1][n][3]*iD);
    }
}

// ============================================================
// launch
// ============================================================
extern "C" void kernel_launch(void* const* d_in, const int* in_sizes, int n_in,
                              void* d_out, int out_size) {
    const float* x      = (const float*)d_in[0];
    const float* w_qkv  = (const float*)d_in[1];
    const float* b_qkv  = (const float*)d_in[2];
    const float* w_proj = (const float*)d_in[3];
    const float* b_proj = (const float*)d_in[4];
    float* out = (float*)d_out;
    (void)in_sizes; (void)n_in; (void)out_size;

    rope_tables_kernel<<<(NTOK*HDIM)/256, 256>>>();

    const int NCONV = MROWS*D_MODEL/4 + (D_MODEL/8*4)*(QKVCOLS/4) + (D_MODEL/8*4)*(D_MODEL/4);
    preconvert_kernel<<<(NCONV + 255)/256, 256>>>(x, w_qkv, w_proj);

    cudaFuncSetAttribute(gemm_tf32_kernel<QKVCOLS, true, 128>,
                         cudaFuncAttributeMaxDynamicSharedMemorySize, GEMM_SMEM(128));
    gemm_tf32_kernel<QKVCOLS, true, 128>
        <<<dim3(QKVCOLS/128, MROWS/128), 256, GEMM_SMEM(128)>>>(b_qkv, nullptr);

    cudaFuncSetAttribute(flash_tf32_kernel,
                         cudaFuncAttributeMaxDynamicSharedMemorySize, FLASH_SMEM);
    flash_tf32_kernel<<<dim3(NTOK/128, BATCH*NHEADS), 128, FLASH_SMEM>>>();

    cudaFuncSetAttribute(gemm_tf32_kernel<D_MODEL, false, 64>,
                         cudaFuncAttributeMaxDynamicSharedMemorySize, GEMM_SMEM(64));
    gemm_tf32_kernel<D_MODEL, false, 64>
        <<<dim3(D_MODEL/128, MROWS/64), 256, GEMM_SMEM(64)>>>(b_proj, out);
}